// round 7
// baseline (speedup 1.0000x reference)
#include <cuda_runtime.h>
#include <cstdint>

// Causal prefill attention, q,k,v,out: [B,H,L,D] fp32. B=2 H=16 L=2048 D=128.
// Flash-attention-2, tf32 mma.sync.m16n8k8, BR=128 (8 warps), BC=64.
// K/V double-buffered via cp.async.cg (raw fp32; HMMA.TF32 truncates internally),
// Q staged once (RNA-rounded), P relaid out C-frag -> A-frag via quad shuffles.

namespace {
constexpr int kL = 2048, kD = 128;
constexpr int BR = 128, BC = 64, NTHR = 256;
constexpr int KSTR = 132;   // %32==4 -> conflict-free Q/K fragment LDS
constexpr int VSTR = 136;   // %32==8 -> conflict-free V fragment LDS
constexpr float kScaleLog2 = 0.12751745210670913f;  // (1/sqrt(128))*log2(e)

constexpr int QTILE = BR * KSTR;            // 16896 floats
constexpr int KTILE = BC * KSTR;            // 8448
constexpr int VTILE = BC * VSTR;            // 8704
// smem float offsets: Q | K0 | K1 | V0 | V1
constexpr int OFF_Q  = 0;
constexpr int OFF_K0 = QTILE;
constexpr int OFF_K1 = OFF_K0 + KTILE;
constexpr int OFF_V0 = OFF_K1 + KTILE;
constexpr int OFF_V1 = OFF_V0 + VTILE;
constexpr int SMEM_FLOATS = OFF_V1 + VTILE; // 51200 floats = 204800 B
}

__device__ __forceinline__ float to_tf32(float x) {
    unsigned u;
    asm("cvt.rna.tf32.f32 %0, %1;" : "=r"(u) : "f"(x));
    return __uint_as_float(u);
}
__device__ __forceinline__ float fast_ex2(float x) {
    float y;
    asm("ex2.approx.f32 %0, %1;" : "=f"(y) : "f"(x));
    return y;
}
__device__ __forceinline__ uint32_t smem_u32(const void* p) {
    uint32_t a;
    asm("{ .reg .u64 t; cvta.to.shared.u64 t, %1; cvt.u32.u64 %0, t; }" : "=r"(a) : "l"(p));
    return a;
}

__device__ __forceinline__ void mma_tf32(float c[4], const float a[4], float b0f, float b1f) {
    unsigned A0 = __float_as_uint(a[0]), A1 = __float_as_uint(a[1]);
    unsigned A2 = __float_as_uint(a[2]), A3 = __float_as_uint(a[3]);
    unsigned B0 = __float_as_uint(b0f), B1 = __float_as_uint(b1f);
    asm volatile(
        "mma.sync.aligned.m16n8k8.row.col.f32.tf32.tf32.f32 "
        "{%0,%1,%2,%3}, {%4,%5,%6,%7}, {%8,%9}, {%0,%1,%2,%3};\n"
        : "+f"(c[0]), "+f"(c[1]), "+f"(c[2]), "+f"(c[3])
        : "r"(A0), "r"(A1), "r"(A2), "r"(A3), "r"(B0), "r"(B1));
}

// async-stage one K tile and one V tile (raw fp32, 16B copies)
__device__ __forceinline__ void stage_kv_async(uint32_t sK, uint32_t sV,
                                               const float* __restrict__ gk,
                                               const float* __restrict__ gv,
                                               size_t base, int k0, int tid) {
    #pragma unroll
    for (int i = 0; i < (BC * kD / 4) / NTHR; ++i) {   // 8
        int lin = tid + i * NTHR;
        int r = lin >> 5, d4 = (lin & 31) << 2;
        const float* pk = &gk[base + (size_t)(k0 + r) * kD + d4];
        const float* pv = &gv[base + (size_t)(k0 + r) * kD + d4];
        uint32_t dk = sK + (uint32_t)(r * KSTR + d4) * 4u;
        uint32_t dv = sV + (uint32_t)(r * VSTR + d4) * 4u;
        asm volatile("cp.async.cg.shared.global [%0], [%1], 16;" :: "r"(dk), "l"(pk));
        asm volatile("cp.async.cg.shared.global [%0], [%1], 16;" :: "r"(dv), "l"(pv));
    }
    asm volatile("cp.async.commit_group;" ::: "memory");
}

__global__ __launch_bounds__(NTHR, 1)
void fa_tf32_async_kernel(const float* __restrict__ gq,
                          const float* __restrict__ gk,
                          const float* __restrict__ gv,
                          float* __restrict__ gout) {
    extern __shared__ float sm[];
    const uint32_t sbase = smem_u32(sm);
    float* Qs = sm + OFF_Q;

    const int tid  = threadIdx.x;
    const int lane = tid & 31;
    const int wid  = tid >> 5;            // 0..7, warp owns 16 query rows
    const int g    = lane >> 2;           // 0..7
    const int lq   = lane & 3;            // 0..3
    const bool odd = (lq & 1);
    const int srcA = (lane & ~3) | (lq >> 1);   // quad shuffle sources
    const int srcB = srcA | 2;

    const int it = (int)gridDim.x - 1 - (int)blockIdx.x;   // heavy tiles first
    const int bh = blockIdx.y;
    const size_t base = (size_t)bh * kL * kD;
    const int q0 = it * BR;

    // ---- stage Q tile (RNA tf32-rounded), normal stores ----
    #pragma unroll
    for (int i = 0; i < (BR * kD / 4) / NTHR; ++i) {   // 16
        int lin = tid + i * NTHR;
        int r = lin >> 5, d4 = (lin & 31) << 2;
        float4 t = *reinterpret_cast<const float4*>(&gq[base + (size_t)(q0 + r) * kD + d4]);
        t.x = to_tf32(t.x); t.y = to_tf32(t.y); t.z = to_tf32(t.z); t.w = to_tf32(t.w);
        *reinterpret_cast<float4*>(&Qs[r * KSTR + d4]) = t;
    }

    const int njt = 2 * it + 2;
    // ---- prologue: async-stage tile 0 into buffer 0 ----
    stage_kv_async(sbase + OFF_K0 * 4u, sbase + OFF_V0 * 4u, gk, gv, base, 0, tid);

    float o[16][4];
    #pragma unroll
    for (int j = 0; j < 16; ++j) { o[j][0] = o[j][1] = o[j][2] = o[j][3] = 0.f; }
    float m0 = -1e30f, m1 = -1e30f;
    float l0 = 0.f, l1 = 0.f;

    const int Rg = wid * 16 + g;
    const int row0 = q0 + Rg, row1 = row0 + 8;

    for (int jt = 0; jt < njt; ++jt) {
        const int k0 = jt * BC;
        const int kb = (jt & 1) ? OFF_K1 : OFF_K0;
        const int vb = (jt & 1) ? OFF_V1 : OFF_V0;

        // ---- async-stage next tile into the other buffer, then wait for this one ----
        if (jt + 1 < njt) {
            stage_kv_async(sbase + ((jt & 1) ? OFF_K0 : OFF_K1) * 4u,
                           sbase + ((jt & 1) ? OFF_V0 : OFF_V1) * 4u,
                           gk, gv, base, k0 + BC, tid);
            asm volatile("cp.async.wait_group 1;" ::: "memory");
        } else {
            asm volatile("cp.async.wait_group 0;" ::: "memory");
        }
        __syncthreads();   // tile jt resident; Q visible (jt==0); all warps done with prior buf

        const float* Ks = sm + kb;
        const float* Vs = sm + vb;

        // ---- GEMM1: S[16x64] = Q K^T (warp-local rows) ----
        float s[8][4];
        #pragma unroll
        for (int j = 0; j < 8; ++j) { s[j][0] = s[j][1] = s[j][2] = s[j][3] = 0.f; }

        #pragma unroll 4
        for (int kk = 0; kk < 16; ++kk) {
            float a[4];
            const float* qa = &Qs[Rg * KSTR + 8 * kk + lq];
            a[0] = qa[0];
            a[1] = qa[8 * KSTR];
            a[2] = qa[4];
            a[3] = qa[8 * KSTR + 4];
            #pragma unroll
            for (int j = 0; j < 8; ++j) {
                const float* kp = &Ks[(8 * j + g) * KSTR + 8 * kk + lq];
                mma_tf32(s[j], a, kp[0], kp[4]);
            }
        }

        // ---- scale (log2 domain) + causal mask on the two diagonal tiles ----
        const bool diag = (jt >= 2 * it);
        float t0 = -1e30f, t1 = -1e30f;
        #pragma unroll
        for (int j = 0; j < 8; ++j) {
            #pragma unroll
            for (int c = 0; c < 4; ++c) s[j][c] *= kScaleLog2;
            if (diag) {
                int col = k0 + 8 * j + 2 * lq;
                if (col     > row0) s[j][0] = -1e30f;
                if (col + 1 > row0) s[j][1] = -1e30f;
                if (col     > row1) s[j][2] = -1e30f;
                if (col + 1 > row1) s[j][3] = -1e30f;
            }
            t0 = fmaxf(t0, fmaxf(s[j][0], s[j][1]));
            t1 = fmaxf(t1, fmaxf(s[j][2], s[j][3]));
        }
        t0 = fmaxf(t0, __shfl_xor_sync(0xffffffffu, t0, 1));
        t0 = fmaxf(t0, __shfl_xor_sync(0xffffffffu, t0, 2));
        t1 = fmaxf(t1, __shfl_xor_sync(0xffffffffu, t1, 1));
        t1 = fmaxf(t1, __shfl_xor_sync(0xffffffffu, t1, 2));

        const float mn0 = fmaxf(m0, t0), mn1 = fmaxf(m1, t1);
        const float al0 = fast_ex2(m0 - mn0), al1 = fast_ex2(m1 - mn1);
        m0 = mn0; m1 = mn1;

        float rs0 = 0.f, rs1 = 0.f;
        #pragma unroll
        for (int j = 0; j < 8; ++j) {
            float p0 = to_tf32(fast_ex2(s[j][0] - mn0));
            float p1 = to_tf32(fast_ex2(s[j][1] - mn0));
            float p2 = to_tf32(fast_ex2(s[j][2] - mn1));
            float p3 = to_tf32(fast_ex2(s[j][3] - mn1));
            rs0 += p0 + p1;
            rs1 += p2 + p3;
            s[j][0] = p0; s[j][1] = p1; s[j][2] = p2; s[j][3] = p3;
        }
        rs0 += __shfl_xor_sync(0xffffffffu, rs0, 1);
        rs0 += __shfl_xor_sync(0xffffffffu, rs0, 2);
        rs1 += __shfl_xor_sync(0xffffffffu, rs1, 1);
        rs1 += __shfl_xor_sync(0xffffffffu, rs1, 2);
        l0 = l0 * al0 + rs0;
        l1 = l1 * al1 + rs1;
        #pragma unroll
        for (int j = 0; j < 16; ++j) {
            o[j][0] *= al0; o[j][1] *= al0;
            o[j][2] *= al1; o[j][3] *= al1;
        }

        // ---- GEMM2: O[16x128] += P V; P C-frag -> A-frag via quad shuffles ----
        #pragma unroll 2
        for (int kk = 0; kk < 8; ++kk) {
            float u0 = __shfl_sync(0xffffffffu, s[kk][0], srcA);
            float u1 = __shfl_sync(0xffffffffu, s[kk][1], srcA);
            float w0 = __shfl_sync(0xffffffffu, s[kk][2], srcA);
            float w1 = __shfl_sync(0xffffffffu, s[kk][3], srcA);
            float v0 = __shfl_sync(0xffffffffu, s[kk][0], srcB);
            float v1 = __shfl_sync(0xffffffffu, s[kk][1], srcB);
            float x0 = __shfl_sync(0xffffffffu, s[kk][2], srcB);
            float x1 = __shfl_sync(0xffffffffu, s[kk][3], srcB);
            float a[4];
            a[0] = odd ? u1 : u0;
            a[1] = odd ? w1 : w0;
            a[2] = odd ? v1 : v0;
            a[3] = odd ? x1 : x0;
            #pragma unroll
            for (int j = 0; j < 16; ++j) {
                const float* vp = &Vs[(8 * kk + lq) * VSTR + 8 * j + g];
                mma_tf32(o[j], a, vp[0], vp[4 * VSTR]);
            }
        }
        __syncthreads();   // all warps done reading buf jt before it is re-staged
    }

    // ---- finalize: divide by l, write out ----
    const float inv0 = 1.0f / l0;
    const float inv1 = 1.0f / l1;
    const size_t r0off = base + (size_t)row0 * kD;
    const size_t r1off = base + (size_t)row1 * kD;
    #pragma unroll
    for (int j = 0; j < 16; ++j) {
        float2 w0; w0.x = o[j][0] * inv0; w0.y = o[j][1] * inv0;
        float2 w1; w1.x = o[j][2] * inv1; w1.y = o[j][3] * inv1;
        *reinterpret_cast<float2*>(&gout[r0off + 8 * j + 2 * lq]) = w0;
        *reinterpret_cast<float2*>(&gout[r1off + 8 * j + 2 * lq]) = w1;
    }
}

extern "C" void kernel_launch(void* const* d_in, const int* in_sizes, int n_in,
                              void* d_out, int out_size) {
    (void)in_sizes; (void)n_in; (void)out_size;
    const float* q = (const float*)d_in[0];
    const float* k = (const float*)d_in[1];
    const float* v = (const float*)d_in[2];
    float* out = (float*)d_out;

    const size_t smem = (size_t)SMEM_FLOATS * sizeof(float);   // 204800 B
    cudaFuncSetAttribute(fa_tf32_async_kernel,
                         cudaFuncAttributeMaxDynamicSharedMemorySize, (int)smem);

    dim3 grid(kL / BR, 32);   // 16 q-tiles x (B*H = 32)
    fa_tf32_async_kernel<<<grid, NTHR, smem>>>(q, k, v, out);
}

// round 8
// speedup vs baseline: 1.0560x; 1.0560x over previous
#include <cuda_runtime.h>
#include <cstdint>

// Causal prefill attention, q,k,v,out: [B,H,L,D] fp32. B=2 H=16 L=2048 D=128.
// Flash-attention-2, tf32 mma.sync.m16n8k8.
// 512 threads (16 warps): warp pair (rg, half) splits each 16-row group's columns.
// K double-buffered + V single-buffered via cp.async.ca; P via smem (RNA tf32).
// Q RNA-rounded once; K/V fed raw fp32 (HMMA.TF32 truncates internally).

namespace {
constexpr int kL = 2048, kD = 128;
constexpr int BR = 128, BC = 64, NTHR = 512;
constexpr int QSTR = 132, KSTR = 132, VSTR = 136, PSTR = 68;
constexpr float kScaleLog2 = 0.12751745210670913f;  // (1/sqrt(128))*log2(e)

constexpr int OFF_Q  = 0;                       // [128][132]
constexpr int OFF_K0 = OFF_Q + BR * QSTR;       // [64][132]
constexpr int OFF_K1 = OFF_K0 + BC * KSTR;      // [64][132]
constexpr int OFF_V  = OFF_K1 + BC * KSTR;      // [64][136]
constexpr int OFF_P  = OFF_V + BC * VSTR;       // [128][68]
constexpr int OFF_MX = OFF_P + BR * PSTR;       // [2][128] partial row max
constexpr int OFF_SM = OFF_MX + 2 * BR;         // [2][128] partial row sum
constexpr int SMEM_FLOATS = OFF_SM + 2 * BR;    // 51712 floats = 206848 B
}

__device__ __forceinline__ float to_tf32(float x) {
    unsigned u;
    asm("cvt.rna.tf32.f32 %0, %1;" : "=r"(u) : "f"(x));
    return __uint_as_float(u);
}
__device__ __forceinline__ float fast_ex2(float x) {
    float y;
    asm("ex2.approx.f32 %0, %1;" : "=f"(y) : "f"(x));
    return y;
}
__device__ __forceinline__ uint32_t smem_u32(const void* p) {
    uint32_t a;
    asm("{ .reg .u64 t; cvta.to.shared.u64 t, %1; cvt.u32.u64 %0, t; }" : "=r"(a) : "l"(p));
    return a;
}
__device__ __forceinline__ void mma_tf32(float c[4], const float a[4], float b0f, float b1f) {
    unsigned A0 = __float_as_uint(a[0]), A1 = __float_as_uint(a[1]);
    unsigned A2 = __float_as_uint(a[2]), A3 = __float_as_uint(a[3]);
    unsigned B0 = __float_as_uint(b0f), B1 = __float_as_uint(b1f);
    asm volatile(
        "mma.sync.aligned.m16n8k8.row.col.f32.tf32.tf32.f32 "
        "{%0,%1,%2,%3}, {%4,%5,%6,%7}, {%8,%9}, {%0,%1,%2,%3};\n"
        : "+f"(c[0]), "+f"(c[1]), "+f"(c[2]), "+f"(c[3])
        : "r"(A0), "r"(A1), "r"(A2), "r"(A3), "r"(B0), "r"(B1));
}

// async-stage one 64x128 fp32 tile (16B copies, L1-caching path)
__device__ __forceinline__ void stage_async(uint32_t dst_bytes, const float* __restrict__ src,
                                            size_t base, int k0, int stride, int tid) {
    #pragma unroll
    for (int i = 0; i < (BC * kD / 4) / NTHR; ++i) {   // 4 per thread
        int lin = tid + i * NTHR;
        int r = lin >> 5, d4 = (lin & 31) << 2;
        const float* p = &src[base + (size_t)(k0 + r) * kD + d4];
        uint32_t d = dst_bytes + (uint32_t)(r * stride + d4) * 4u;
        asm volatile("cp.async.ca.shared.global [%0], [%1], 16;" :: "r"(d), "l"(p));
    }
    asm volatile("cp.async.commit_group;" ::: "memory");
}

__global__ __launch_bounds__(NTHR, 1)
void fa_tf32_w16_kernel(const float* __restrict__ gq,
                        const float* __restrict__ gk,
                        const float* __restrict__ gv,
                        float* __restrict__ gout) {
    extern __shared__ float sm[];
    const uint32_t sb = smem_u32(sm);
    float* Qs = sm + OFF_Q;
    float* Vs = sm + OFF_V;
    float* Pp = sm + OFF_P;

    const int tid  = threadIdx.x;
    const int lane = tid & 31;
    const int wid  = tid >> 5;            // 0..15
    const int rg   = wid >> 1;            // row-group 0..7 (16 rows each)
    const int half = wid & 1;             // column half (S: 32 cols, O: 64 cols)
    const int g    = lane >> 2;           // 0..7
    const int lq   = lane & 3;            // 0..3

    const int it = (int)gridDim.x - 1 - (int)blockIdx.x;   // heavy tiles first
    const int bh = blockIdx.y;
    const size_t base = (size_t)bh * kL * kD;
    const int q0 = it * BR;
    const int Rg = rg * 16 + g;           // local row
    const int row0 = q0 + Rg, row1 = row0 + 8;

    // ---- stage Q tile (RNA tf32), 8 float4 per thread ----
    #pragma unroll
    for (int i = 0; i < (BR * kD / 4) / NTHR; ++i) {
        int lin = tid + i * NTHR;
        int r = lin >> 5, d4 = (lin & 31) << 2;
        float4 t = *reinterpret_cast<const float4*>(&gq[base + (size_t)(q0 + r) * kD + d4]);
        t.x = to_tf32(t.x); t.y = to_tf32(t.y); t.z = to_tf32(t.z); t.w = to_tf32(t.w);
        *reinterpret_cast<float4*>(&Qs[r * QSTR + d4]) = t;
    }

    // ---- prologue: async-stage K(0) into buffer 0 ----
    stage_async(sb + OFF_K0 * 4u, gk, base, 0, KSTR, tid);

    float o[8][4];
    #pragma unroll
    for (int j = 0; j < 8; ++j) { o[j][0] = o[j][1] = o[j][2] = o[j][3] = 0.f; }
    float m0 = -1e30f, m1 = -1e30f, l0 = 0.f, l1 = 0.f;

    const int njt = 2 * it + 2;
    for (int jt = 0; jt < njt; ++jt) {
        const int k0 = jt * BC;
        const bool havek = (jt + 1 < njt);

        // issue V(jt); issue K(jt+1) into the other K buffer
        stage_async(sb + OFF_V * 4u, gv, base, k0, VSTR, tid);
        if (havek)
            stage_async(sb + ((jt & 1) ? OFF_K0 : OFF_K1) * 4u, gk, base, k0 + BC, KSTR, tid);

        // K(jt) resident (groups retire in order)
        if (havek) asm volatile("cp.async.wait_group 2;" ::: "memory");
        else       asm volatile("cp.async.wait_group 1;" ::: "memory");
        __syncthreads();

        const float* Ks = sm + ((jt & 1) ? OFF_K1 : OFF_K0);

        // ---- GEMM1: S[16 x 32(half)] = Q K^T ----
        float s[4][4];
        #pragma unroll
        for (int j = 0; j < 4; ++j) { s[j][0] = s[j][1] = s[j][2] = s[j][3] = 0.f; }
        #pragma unroll 4
        for (int kk = 0; kk < 16; ++kk) {
            float a[4];
            const float* qa = &Qs[Rg * QSTR + 8 * kk + lq];
            a[0] = qa[0];
            a[1] = qa[8 * QSTR];
            a[2] = qa[4];
            a[3] = qa[8 * QSTR + 4];
            #pragma unroll
            for (int j = 0; j < 4; ++j) {
                const float* kp = &Ks[(half * 32 + 8 * j + g) * KSTR + 8 * kk + lq];
                mma_tf32(s[j], a, kp[0], kp[4]);
            }
        }

        // ---- scale (log2) + causal mask + partial row max ----
        const bool diag = (jt >= 2 * it);
        float t0 = -1e30f, t1 = -1e30f;
        #pragma unroll
        for (int j = 0; j < 4; ++j) {
            #pragma unroll
            for (int c = 0; c < 4; ++c) s[j][c] *= kScaleLog2;
            if (diag) {
                int col = k0 + half * 32 + 8 * j + 2 * lq;
                if (col     > row0) s[j][0] = -1e30f;
                if (col + 1 > row0) s[j][1] = -1e30f;
                if (col     > row1) s[j][2] = -1e30f;
                if (col + 1 > row1) s[j][3] = -1e30f;
            }
            t0 = fmaxf(t0, fmaxf(s[j][0], s[j][1]));
            t1 = fmaxf(t1, fmaxf(s[j][2], s[j][3]));
        }
        t0 = fmaxf(t0, __shfl_xor_sync(0xffffffffu, t0, 1));
        t0 = fmaxf(t0, __shfl_xor_sync(0xffffffffu, t0, 2));
        t1 = fmaxf(t1, __shfl_xor_sync(0xffffffffu, t1, 1));
        t1 = fmaxf(t1, __shfl_xor_sync(0xffffffffu, t1, 2));
        if (lq == 0) {
            sm[OFF_MX + half * BR + Rg]     = t0;
            sm[OFF_MX + half * BR + Rg + 8] = t1;
        }
        __syncthreads();

        // combine max across the warp pair
        const float tm0 = fmaxf(t0, sm[OFF_MX + (1 - half) * BR + Rg]);
        const float tm1 = fmaxf(t1, sm[OFF_MX + (1 - half) * BR + Rg + 8]);
        const float mn0 = fmaxf(m0, tm0), mn1 = fmaxf(m1, tm1);
        const float al0 = fast_ex2(m0 - mn0), al1 = fast_ex2(m1 - mn1);
        m0 = mn0; m1 = mn1;

        // ---- exp (RNA tf32), write P, partial sums ----
        float rs0 = 0.f, rs1 = 0.f;
        #pragma unroll
        for (int j = 0; j < 4; ++j) {
            float p0 = to_tf32(fast_ex2(s[j][0] - mn0));
            float p1 = to_tf32(fast_ex2(s[j][1] - mn0));
            float p2 = to_tf32(fast_ex2(s[j][2] - mn1));
            float p3 = to_tf32(fast_ex2(s[j][3] - mn1));
            rs0 += p0 + p1;
            rs1 += p2 + p3;
            int pc = half * 32 + 8 * j + 2 * lq;
            float2 w0; w0.x = p0; w0.y = p1;
            float2 w1; w1.x = p2; w1.y = p3;
            *reinterpret_cast<float2*>(&Pp[Rg * PSTR + pc])       = w0;
            *reinterpret_cast<float2*>(&Pp[(Rg + 8) * PSTR + pc]) = w1;
        }
        rs0 += __shfl_xor_sync(0xffffffffu, rs0, 1);
        rs0 += __shfl_xor_sync(0xffffffffu, rs0, 2);
        rs1 += __shfl_xor_sync(0xffffffffu, rs1, 1);
        rs1 += __shfl_xor_sync(0xffffffffu, rs1, 2);
        if (lq == 0) {
            sm[OFF_SM + half * BR + Rg]     = rs0;
            sm[OFF_SM + half * BR + Rg + 8] = rs1;
        }
        // rescale O (independent of the exchanges)
        #pragma unroll
        for (int j = 0; j < 8; ++j) {
            o[j][0] *= al0; o[j][1] *= al0;
            o[j][2] *= al1; o[j][3] *= al1;
        }

        // V(jt) resident before GEMM2
        if (havek) asm volatile("cp.async.wait_group 1;" ::: "memory");
        else       asm volatile("cp.async.wait_group 0;" ::: "memory");
        __syncthreads();   // P + partial sums + V visible

        l0 = l0 * al0 + rs0 + sm[OFF_SM + (1 - half) * BR + Rg];
        l1 = l1 * al1 + rs1 + sm[OFF_SM + (1 - half) * BR + Rg + 8];

        // ---- GEMM2: O[16 x 64(half)] += P V ----
        #pragma unroll 2
        for (int kk = 0; kk < 8; ++kk) {
            float a[4];
            const float* pa = &Pp[Rg * PSTR + 8 * kk + lq];
            a[0] = pa[0];
            a[1] = pa[8 * PSTR];
            a[2] = pa[4];
            a[3] = pa[8 * PSTR + 4];
            #pragma unroll
            for (int j = 0; j < 8; ++j) {
                const float* vp = &Vs[(8 * kk + lq) * VSTR + half * 64 + 8 * j + g];
                mma_tf32(o[j], a, vp[0], vp[4 * VSTR]);
            }
        }
        __syncthreads();   // all warps done with V / P before next iteration re-stages
    }

    // ---- finalize: divide by l, write out ----
    const float inv0 = 1.0f / l0;
    const float inv1 = 1.0f / l1;
    const size_t r0off = base + (size_t)row0 * kD;
    const size_t r1off = base + (size_t)row1 * kD;
    #pragma unroll
    for (int j = 0; j < 8; ++j) {
        int col = half * 64 + 8 * j + 2 * lq;
        float2 w0; w0.x = o[j][0] * inv0; w0.y = o[j][1] * inv0;
        float2 w1; w1.x = o[j][2] * inv1; w1.y = o[j][3] * inv1;
        *reinterpret_cast<float2*>(&gout[r0off + col]) = w0;
        *reinterpret_cast<float2*>(&gout[r1off + col]) = w1;
    }
}

extern "C" void kernel_launch(void* const* d_in, const int* in_sizes, int n_in,
                              void* d_out, int out_size) {
    (void)in_sizes; (void)n_in; (void)out_size;
    const float* q = (const float*)d_in[0];
    const float* k = (const float*)d_in[1];
    const float* v = (const float*)d_in[2];
    float* out = (float*)d_out;

    const size_t smem = (size_t)SMEM_FLOATS * sizeof(float);   // 206848 B
    cudaFuncSetAttribute(fa_tf32_w16_kernel,
                         cudaFuncAttributeMaxDynamicSharedMemorySize, (int)smem);

    dim3 grid(kL / BR, 32);   // 16 q-tiles x (B*H = 32)
    fa_tf32_w16_kernel<<<grid, NTHR, smem>>>(q, k, v, out);
}

// round 9
// speedup vs baseline: 1.2039x; 1.1401x over previous
#include <cuda_runtime.h>
#include <cstdint>

// Causal prefill attention, q,k,v,out: [B,H,L,D] fp32. B=2 H=16 L=2048 D=128.
// Flash-attention-2, tf32 mma.sync.m16n8k8, BR=128, BC=64, 8 warps.
// Warp (rg, half) = 32 query rows x 32-key half: independent per-warp online
// softmax (no cross-warp exchanges in the loop); one O/l/m merge at the end.
// K double-buffered + V single-buffered via cp.async.ca. 2 barriers/iter.

namespace {
constexpr int kL = 2048, kD = 128;
constexpr int BR = 128, BC = 64, NTHR = 256;
constexpr int QSTR = 132, KSTR = 132, VSTR = 136, PSTR = 36;
constexpr float kScaleLog2 = 0.12751745210670913f;  // (1/sqrt(128))*log2(e)

constexpr int OFF_Q  = 0;                        // [128][132]
constexpr int OFF_K0 = OFF_Q + BR * QSTR;        // 16896
constexpr int OFF_K1 = OFF_K0 + BC * KSTR;       // 25344
constexpr int OFF_V  = OFF_K1 + BC * KSTR;       // 33792  [64][136]
constexpr int OFF_P  = OFF_V + BC * VSTR;        // 42496  8 x [32][36] per-warp
constexpr int OFF_ML = OFF_P + 8 * 32 * PSTR;    // 51712  [2][128][2] (m,l)
constexpr int SMEM_FLOATS = OFF_ML + 512;        // 52224 floats = 208896 B
constexpr int OFF_MRG = OFF_K0;                  // end-of-kernel merge buffer [128][132]
}

__device__ __forceinline__ float to_tf32(float x) {
    unsigned u;
    asm("cvt.rna.tf32.f32 %0, %1;" : "=r"(u) : "f"(x));
    return __uint_as_float(u);
}
__device__ __forceinline__ float fast_ex2(float x) {
    float y;
    asm("ex2.approx.f32 %0, %1;" : "=f"(y) : "f"(x));
    return y;
}
__device__ __forceinline__ uint32_t smem_u32(const void* p) {
    uint32_t a;
    asm("{ .reg .u64 t; cvta.to.shared.u64 t, %1; cvt.u32.u64 %0, t; }" : "=r"(a) : "l"(p));
    return a;
}
__device__ __forceinline__ void mma_tf32(float c[4], const float a[4], float b0f, float b1f) {
    unsigned A0 = __float_as_uint(a[0]), A1 = __float_as_uint(a[1]);
    unsigned A2 = __float_as_uint(a[2]), A3 = __float_as_uint(a[3]);
    unsigned B0 = __float_as_uint(b0f), B1 = __float_as_uint(b1f);
    asm volatile(
        "mma.sync.aligned.m16n8k8.row.col.f32.tf32.tf32.f32 "
        "{%0,%1,%2,%3}, {%4,%5,%6,%7}, {%8,%9}, {%0,%1,%2,%3};\n"
        : "+f"(c[0]), "+f"(c[1]), "+f"(c[2]), "+f"(c[3])
        : "r"(A0), "r"(A1), "r"(A2), "r"(A3), "r"(B0), "r"(B1));
}

// async-stage one 64x128 fp32 tile (16B copies, L1-caching path), then commit
__device__ __forceinline__ void stage_async(uint32_t dst_bytes, const float* __restrict__ src,
                                            size_t base, int k0, int stride, int tid) {
    #pragma unroll
    for (int i = 0; i < (BC * kD / 4) / NTHR; ++i) {   // 8 per thread
        int lin = tid + i * NTHR;
        int r = lin >> 5, d4 = (lin & 31) << 2;
        const float* p = &src[base + (size_t)(k0 + r) * kD + d4];
        uint32_t d = dst_bytes + (uint32_t)(r * stride + d4) * 4u;
        asm volatile("cp.async.ca.shared.global [%0], [%1], 16;" :: "r"(d), "l"(p));
    }
    asm volatile("cp.async.commit_group;" ::: "memory");
}

__global__ __launch_bounds__(NTHR, 1)
void fa_tf32_ksplit_kernel(const float* __restrict__ gq,
                           const float* __restrict__ gk,
                           const float* __restrict__ gv,
                           float* __restrict__ gout) {
    extern __shared__ float sm[];
    const uint32_t sb = smem_u32(sm);
    float* Qs = sm + OFF_Q;
    float* Vs = sm + OFF_V;

    const int tid  = threadIdx.x;
    const int lane = tid & 31;
    const int wid  = tid >> 5;           // 0..7
    const int rg   = wid >> 1;           // row-group 0..3 (32 rows each)
    const int half = wid & 1;            // key half within each BC tile
    const int g    = lane >> 2;          // 0..7
    const int lq   = lane & 3;           // 0..3
    float* Pw = sm + OFF_P + wid * 32 * PSTR;   // per-warp P [32][36]

    const int it = (int)gridDim.x - 1 - (int)blockIdx.x;   // heavy tiles first
    const int bh = blockIdx.y;
    const size_t base = (size_t)bh * kL * kD;
    const int q0 = it * BR;

    // ---- stage Q tile (RNA tf32) ----
    #pragma unroll
    for (int i = 0; i < (BR * kD / 4) / NTHR; ++i) {   // 16
        int lin = tid + i * NTHR;
        int r = lin >> 5, d4 = (lin & 31) << 2;
        float4 t = *reinterpret_cast<const float4*>(&gq[base + (size_t)(q0 + r) * kD + d4]);
        t.x = to_tf32(t.x); t.y = to_tf32(t.y); t.z = to_tf32(t.z); t.w = to_tf32(t.w);
        *reinterpret_cast<float4*>(&Qs[r * QSTR + d4]) = t;
    }

    // ---- prologue: async-stage K(0) ----
    stage_async(sb + OFF_K0 * 4u, gk, base, 0, KSTR, tid);

    float o[2][16][4];
    #pragma unroll
    for (int rt = 0; rt < 2; ++rt)
        #pragma unroll
        for (int jn = 0; jn < 16; ++jn)
            { o[rt][jn][0] = o[rt][jn][1] = o[rt][jn][2] = o[rt][jn][3] = 0.f; }
    float mm[4] = {-1e30f, -1e30f, -1e30f, -1e30f};   // [2rt+rh]
    float ll[4] = {0.f, 0.f, 0.f, 0.f};

    const int njt = 2 * it + 2;
    for (int jt = 0; jt < njt; ++jt) {
        const int k0 = jt * BC;
        const bool havek = (jt + 1 < njt);

        asm volatile("cp.async.wait_group 0;" ::: "memory");   // K(jt) resident
        __syncthreads();   // K visible to all; everyone done with V(jt-1)

        // issue V(jt) and prefetch K(jt+1)
        stage_async(sb + OFF_V * 4u, gv, base, k0, VSTR, tid);
        if (havek)
            stage_async(sb + ((jt & 1) ? OFF_K0 : OFF_K1) * 4u, gk, base, k0 + BC, KSTR, tid);

        const float* Ks = sm + ((jt & 1) ? OFF_K1 : OFF_K0);

        // ---- GEMM1: S[32 x 32] = Q x K(half)^T ----
        float s[2][4][4];
        #pragma unroll
        for (int rt = 0; rt < 2; ++rt)
            #pragma unroll
            for (int j = 0; j < 4; ++j)
                { s[rt][j][0] = s[rt][j][1] = s[rt][j][2] = s[rt][j][3] = 0.f; }

        #pragma unroll 4
        for (int kk = 0; kk < 16; ++kk) {
            float a[2][4];
            #pragma unroll
            for (int rt = 0; rt < 2; ++rt) {
                const float* qa = &Qs[(32 * rg + 16 * rt + g) * QSTR + 8 * kk + lq];
                a[rt][0] = qa[0];
                a[rt][1] = qa[8 * QSTR];
                a[rt][2] = qa[4];
                a[rt][3] = qa[8 * QSTR + 4];
            }
            #pragma unroll
            for (int j = 0; j < 4; ++j) {
                const float* kp = &Ks[(32 * half + 8 * j + g) * KSTR + 8 * kk + lq];
                float b0 = kp[0], b1 = kp[4];
                mma_tf32(s[0][j], a[0], b0, b1);
                mma_tf32(s[1][j], a[1], b0, b1);
            }
        }

        // ---- warp-local softmax (log2 domain) ----
        const bool diag = (jt >= 2 * it);
        #pragma unroll
        for (int rt = 0; rt < 2; ++rt) {
            const int r0 = q0 + 32 * rg + 16 * rt + g, r1 = r0 + 8;
            float t0 = -1e30f, t1 = -1e30f;
            #pragma unroll
            for (int j = 0; j < 4; ++j) {
                #pragma unroll
                for (int c = 0; c < 4; ++c) s[rt][j][c] *= kScaleLog2;
                if (diag) {
                    int col = k0 + 32 * half + 8 * j + 2 * lq;
                    if (col     > r0) s[rt][j][0] = -1e30f;
                    if (col + 1 > r0) s[rt][j][1] = -1e30f;
                    if (col     > r1) s[rt][j][2] = -1e30f;
                    if (col + 1 > r1) s[rt][j][3] = -1e30f;
                }
                t0 = fmaxf(t0, fmaxf(s[rt][j][0], s[rt][j][1]));
                t1 = fmaxf(t1, fmaxf(s[rt][j][2], s[rt][j][3]));
            }
            t0 = fmaxf(t0, __shfl_xor_sync(0xffffffffu, t0, 1));
            t0 = fmaxf(t0, __shfl_xor_sync(0xffffffffu, t0, 2));
            t1 = fmaxf(t1, __shfl_xor_sync(0xffffffffu, t1, 1));
            t1 = fmaxf(t1, __shfl_xor_sync(0xffffffffu, t1, 2));

            const float mn0 = fmaxf(mm[2 * rt], t0), mn1 = fmaxf(mm[2 * rt + 1], t1);
            const float al0 = fast_ex2(mm[2 * rt] - mn0), al1 = fast_ex2(mm[2 * rt + 1] - mn1);
            // all-masked guard: if this half-row has never seen an unmasked key,
            // ex2(s-mn)=ex2(0)=1 would be garbage -> force p to 0.
            const float v0 = (mn0 > -9.0e29f) ? 1.f : 0.f;
            const float v1 = (mn1 > -9.0e29f) ? 1.f : 0.f;
            mm[2 * rt] = mn0; mm[2 * rt + 1] = mn1;

            float rs0 = 0.f, rs1 = 0.f;
            #pragma unroll
            for (int j = 0; j < 4; ++j) {
                float p0 = to_tf32(fast_ex2(s[rt][j][0] - mn0)) * v0;
                float p1 = to_tf32(fast_ex2(s[rt][j][1] - mn0)) * v0;
                float p2 = to_tf32(fast_ex2(s[rt][j][2] - mn1)) * v1;
                float p3 = to_tf32(fast_ex2(s[rt][j][3] - mn1)) * v1;
                rs0 += p0 + p1;
                rs1 += p2 + p3;
                float2 w0; w0.x = p0; w0.y = p1;
                float2 w1; w1.x = p2; w1.y = p3;
                *reinterpret_cast<float2*>(&Pw[(16 * rt + g) * PSTR + 8 * j + 2 * lq])     = w0;
                *reinterpret_cast<float2*>(&Pw[(16 * rt + g + 8) * PSTR + 8 * j + 2 * lq]) = w1;
            }
            rs0 += __shfl_xor_sync(0xffffffffu, rs0, 1);
            rs0 += __shfl_xor_sync(0xffffffffu, rs0, 2);
            rs1 += __shfl_xor_sync(0xffffffffu, rs1, 1);
            rs1 += __shfl_xor_sync(0xffffffffu, rs1, 2);
            ll[2 * rt]     = ll[2 * rt] * al0 + rs0;
            ll[2 * rt + 1] = ll[2 * rt + 1] * al1 + rs1;
            #pragma unroll
            for (int jn = 0; jn < 16; ++jn) {
                o[rt][jn][0] *= al0; o[rt][jn][1] *= al0;
                o[rt][jn][2] *= al1; o[rt][jn][3] *= al1;
            }
        }
        __syncwarp();   // P visible within the warp

        // ---- V(jt) resident ----
        if (havek) asm volatile("cp.async.wait_group 1;" ::: "memory");
        else       asm volatile("cp.async.wait_group 0;" ::: "memory");
        __syncthreads();

        // ---- GEMM2: O[32 x 128] += P(32x32) x V(half keys) ----
        #pragma unroll
        for (int kk = 0; kk < 4; ++kk) {
            float a[2][4];
            #pragma unroll
            for (int rt = 0; rt < 2; ++rt) {
                const float* pa = &Pw[(16 * rt + g) * PSTR + 8 * kk + lq];
                a[rt][0] = pa[0];
                a[rt][1] = pa[8 * PSTR];
                a[rt][2] = pa[4];
                a[rt][3] = pa[8 * PSTR + 4];
            }
            #pragma unroll
            for (int jn = 0; jn < 16; ++jn) {
                const float* vp = &Vs[(32 * half + 8 * kk + lq) * VSTR + 8 * jn + g];
                float b0 = vp[0], b1 = vp[4 * VSTR];
                mma_tf32(o[0][jn], a[0], b0, b1);
                mma_tf32(o[1][jn], a[1], b0, b1);
            }
        }
    }

    // ================= final merge of the two key-halves =================
    // exchange (m, l) per row
    if (lq == 0) {
        #pragma unroll
        for (int i = 0; i < 4; ++i) {
            int rloc = 32 * rg + 16 * (i >> 1) + g + 8 * (i & 1);
            sm[OFF_ML + half * 256 + 2 * rloc]     = mm[i];
            sm[OFF_ML + half * 256 + 2 * rloc + 1] = ll[i];
        }
    }
    __syncthreads();
    float coef[4];
    #pragma unroll
    for (int i = 0; i < 4; ++i) {
        int rloc = 32 * rg + 16 * (i >> 1) + g + 8 * (i & 1);
        float mo = sm[OFF_ML + (1 - half) * 256 + 2 * rloc];
        float lo = sm[OFF_ML + (1 - half) * 256 + 2 * rloc + 1];
        float ms = fmaxf(mm[i], mo);
        float lt = ll[i] * fast_ex2(mm[i] - ms) + lo * fast_ex2(mo - ms);
        coef[i] = fast_ex2(mm[i] - ms) / lt;
    }
    __syncthreads();   // ML reads done before MRG overwrites nothing (MRG=K bufs, ML separate) — keep for safety

    // half0 deposits its scaled partial O into the (dead) K buffers
    if (half == 0) {
        #pragma unroll
        for (int rt = 0; rt < 2; ++rt)
            #pragma unroll
            for (int jn = 0; jn < 16; ++jn) {
                int d = 8 * jn + 2 * lq;
                int r0 = 32 * rg + 16 * rt + g;
                sm[OFF_MRG + r0 * 132 + d]           = o[rt][jn][0] * coef[2 * rt];
                sm[OFF_MRG + r0 * 132 + d + 1]       = o[rt][jn][1] * coef[2 * rt];
                sm[OFF_MRG + (r0 + 8) * 132 + d]     = o[rt][jn][2] * coef[2 * rt + 1];
                sm[OFF_MRG + (r0 + 8) * 132 + d + 1] = o[rt][jn][3] * coef[2 * rt + 1];
            }
    }
    __syncthreads();
    // half1 adds its part and writes the result
    if (half == 1) {
        #pragma unroll
        for (int rt = 0; rt < 2; ++rt)
            #pragma unroll
            for (int jn = 0; jn < 16; ++jn) {
                int d = 8 * jn + 2 * lq;
                int r0 = 32 * rg + 16 * rt + g;
                float2 w0, w1;
                w0.x = sm[OFF_MRG + r0 * 132 + d]           + o[rt][jn][0] * coef[2 * rt];
                w0.y = sm[OFF_MRG + r0 * 132 + d + 1]       + o[rt][jn][1] * coef[2 * rt];
                w1.x = sm[OFF_MRG + (r0 + 8) * 132 + d]     + o[rt][jn][2] * coef[2 * rt + 1];
                w1.y = sm[OFF_MRG + (r0 + 8) * 132 + d + 1] + o[rt][jn][3] * coef[2 * rt + 1];
                *reinterpret_cast<float2*>(&gout[base + (size_t)(q0 + r0) * kD + d])     = w0;
                *reinterpret_cast<float2*>(&gout[base + (size_t)(q0 + r0 + 8) * kD + d]) = w1;
            }
    }
}

extern "C" void kernel_launch(void* const* d_in, const int* in_sizes, int n_in,
                              void* d_out, int out_size) {
    (void)in_sizes; (void)n_in; (void)out_size;
    const float* q = (const float*)d_in[0];
    const float* k = (const float*)d_in[1];
    const float* v = (const float*)d_in[2];
    float* out = (float*)d_out;

    const size_t smem = (size_t)SMEM_FLOATS * sizeof(float);   // 208896 B
    cudaFuncSetAttribute(fa_tf32_ksplit_kernel,
                         cudaFuncAttributeMaxDynamicSharedMemorySize, (int)smem);

    dim3 grid(kL / BR, 32);   // 16 q-tiles x (B*H = 32)
    fa_tf32_ksplit_kernel<<<grid, NTHR, smem>>>(q, k, v, out);
}

// round 10
// speedup vs baseline: 1.2368x; 1.0273x over previous
#include <cuda_runtime.h>
#include <cstdint>

// Causal prefill attention, q,k,v,out: [B,H,L,D] fp32. B=2 H=16 L=2048 D=128.
// Flash-attention-2, tf32 mma.sync.m16n8k8, BR=128, BC=64, 8 warps.
// Warp (rg, half) = 32 query rows x 32-key half; per-warp online softmax,
// one O/l/m merge at the end. K double-buffered + V single via cp.async.ca.
// NEW (R10): Q/K/P fragments fed by ldmatrix.m8n8.x4 (4 fragments per instr)
// instead of scalar LDS -> 4x fewer dependent loads on the MMA critical path.

namespace {
constexpr int kL = 2048, kD = 128;
constexpr int BR = 128, BC = 64, NTHR = 256;
constexpr int QSTR = 132, KSTR = 132, VSTR = 136, PSTR = 36;
constexpr float kScaleLog2 = 0.12751745210670913f;  // (1/sqrt(128))*log2(e)

constexpr int OFF_Q  = 0;                        // [128][132]
constexpr int OFF_K0 = OFF_Q + BR * QSTR;
constexpr int OFF_K1 = OFF_K0 + BC * KSTR;
constexpr int OFF_V  = OFF_K1 + BC * KSTR;       // [64][136]
constexpr int OFF_P  = OFF_V + BC * VSTR;        // 8 x [32][36] per-warp
constexpr int OFF_ML = OFF_P + 8 * 32 * PSTR;    // [2][128][2] (m,l)
constexpr int SMEM_FLOATS = OFF_ML + 512;        // 52224 floats = 208896 B
constexpr int OFF_MRG = OFF_K0;                  // end-of-kernel merge buffer
}

__device__ __forceinline__ float to_tf32(float x) {
    unsigned u;
    asm("cvt.rna.tf32.f32 %0, %1;" : "=r"(u) : "f"(x));
    return __uint_as_float(u);
}
__device__ __forceinline__ float fast_ex2(float x) {
    float y;
    asm("ex2.approx.f32 %0, %1;" : "=f"(y) : "f"(x));
    return y;
}
__device__ __forceinline__ uint32_t smem_u32(const void* p) {
    uint32_t a;
    asm("{ .reg .u64 t; cvta.to.shared.u64 t, %1; cvt.u32.u64 %0, t; }" : "=r"(a) : "l"(p));
    return a;
}
__device__ __forceinline__ void ldsm_x4(uint32_t r[4], uint32_t addr) {
    asm volatile("ldmatrix.sync.aligned.m8n8.x4.shared.b16 {%0,%1,%2,%3}, [%4];"
                 : "=r"(r[0]), "=r"(r[1]), "=r"(r[2]), "=r"(r[3]) : "r"(addr));
}
__device__ __forceinline__ void mma_tf32(float c[4], const uint32_t a[4],
                                         uint32_t b0, uint32_t b1) {
    asm volatile(
        "mma.sync.aligned.m16n8k8.row.col.f32.tf32.tf32.f32 "
        "{%0,%1,%2,%3}, {%4,%5,%6,%7}, {%8,%9}, {%0,%1,%2,%3};\n"
        : "+f"(c[0]), "+f"(c[1]), "+f"(c[2]), "+f"(c[3])
        : "r"(a[0]), "r"(a[1]), "r"(a[2]), "r"(a[3]), "r"(b0), "r"(b1));
}

// async-stage one 64x128 fp32 tile (16B copies, L1-caching path), then commit
__device__ __forceinline__ void stage_async(uint32_t dst_bytes, const float* __restrict__ src,
                                            size_t base, int k0, int stride, int tid) {
    #pragma unroll
    for (int i = 0; i < (BC * kD / 4) / NTHR; ++i) {   // 8 per thread
        int lin = tid + i * NTHR;
        int r = lin >> 5, d4 = (lin & 31) << 2;
        const float* p = &src[base + (size_t)(k0 + r) * kD + d4];
        uint32_t d = dst_bytes + (uint32_t)(r * stride + d4) * 4u;
        asm volatile("cp.async.ca.shared.global [%0], [%1], 16;" :: "r"(d), "l"(p));
    }
    asm volatile("cp.async.commit_group;" ::: "memory");
}

__global__ __launch_bounds__(NTHR, 1)
void fa_tf32_ldsm_kernel(const float* __restrict__ gq,
                         const float* __restrict__ gk,
                         const float* __restrict__ gv,
                         float* __restrict__ gout) {
    extern __shared__ float sm[];
    const uint32_t sb = smem_u32(sm);
    float* Qs = sm + OFF_Q;
    float* Vs = sm + OFF_V;

    const int tid  = threadIdx.x;
    const int lane = tid & 31;
    const int wid  = tid >> 5;           // 0..7
    const int rg   = wid >> 1;           // row-group 0..3 (32 rows each)
    const int half = wid & 1;            // key half within each BC tile
    const int g    = lane >> 2;          // 0..7
    const int lq   = lane & 3;           // 0..3
    float* Pw = sm + OFF_P + wid * 32 * PSTR;   // per-warp P [32][36]

    // ---- per-lane ldmatrix base addresses (bytes) ----
    const int l15  = lane & 15;           // row within 16-row block (tiles 0/1 vs 2/3)
    const int chi  = (lane >> 4) & 1;     // col half selector for A-pattern tiles
    // Q A-fragments: tiles (rows 0-7, col lo), (rows 8-15, lo), (0-7, hi), (8-15, hi)
    const uint32_t qb0 = sb + (uint32_t)(((32 * rg + l15) * QSTR + 4 * chi) * 4) + OFF_Q * 4u;
    const uint32_t qb1 = qb0 + (uint32_t)(16 * QSTR * 4);
    // P A-fragments: same pattern on the per-warp P tile
    const uint32_t pwb = sb + (uint32_t)((OFF_P + wid * 32 * PSTR) * 4);
    const uint32_t pb0 = pwb + (uint32_t)((l15 * PSTR + 4 * chi) * 4);
    const uint32_t pb1 = pb0 + (uint32_t)(16 * PSTR * 4);
    // K B-fragments: tiles (j=2p, col lo), (j=2p, hi), (j=2p+1, lo), (j=2p+1, hi)
    const int jsel = (lane >> 4) & 1;     // tile pair selector (j within pair)
    const int csel = (lane >> 3) & 1;     // col half selector
    const uint32_t krow_off =
        (uint32_t)(((32 * half + 8 * jsel + (lane & 7)) * KSTR + 4 * csel) * 4);

    const int it = (int)gridDim.x - 1 - (int)blockIdx.x;   // heavy tiles first
    const int bh = blockIdx.y;
    const size_t base = (size_t)bh * kL * kD;
    const int q0 = it * BR;

    // ---- stage Q tile (RNA tf32) ----
    #pragma unroll
    for (int i = 0; i < (BR * kD / 4) / NTHR; ++i) {   // 16
        int lin = tid + i * NTHR;
        int r = lin >> 5, d4 = (lin & 31) << 2;
        float4 t = *reinterpret_cast<const float4*>(&gq[base + (size_t)(q0 + r) * kD + d4]);
        t.x = to_tf32(t.x); t.y = to_tf32(t.y); t.z = to_tf32(t.z); t.w = to_tf32(t.w);
        *reinterpret_cast<float4*>(&Qs[r * QSTR + d4]) = t;
    }

    // ---- prologue: async-stage K(0) ----
    stage_async(sb + OFF_K0 * 4u, gk, base, 0, KSTR, tid);

    float o[2][16][4];
    #pragma unroll
    for (int rt = 0; rt < 2; ++rt)
        #pragma unroll
        for (int jn = 0; jn < 16; ++jn)
            { o[rt][jn][0] = o[rt][jn][1] = o[rt][jn][2] = o[rt][jn][3] = 0.f; }
    float mm[4] = {-1e30f, -1e30f, -1e30f, -1e30f};
    float ll[4] = {0.f, 0.f, 0.f, 0.f};

    const int njt = 2 * it + 2;
    for (int jt = 0; jt < njt; ++jt) {
        const int k0 = jt * BC;
        const bool havek = (jt + 1 < njt);

        asm volatile("cp.async.wait_group 0;" ::: "memory");   // K(jt) resident
        __syncthreads();   // K visible; everyone done with V(jt-1)

        // issue V(jt); prefetch K(jt+1)
        stage_async(sb + OFF_V * 4u, gv, base, k0, VSTR, tid);
        if (havek)
            stage_async(sb + ((jt & 1) ? OFF_K0 : OFF_K1) * 4u, gk, base, k0 + BC, KSTR, tid);

        const uint32_t kbuf = sb + (uint32_t)(((jt & 1) ? OFF_K1 : OFF_K0) * 4);
        const uint32_t kb0 = kbuf + krow_off;                   // j pair 0 (j=0,1)
        const uint32_t kb1 = kb0 + (uint32_t)(16 * KSTR * 4);   // j pair 1 (j=2,3)

        // ---- GEMM1: S[32 x 32] = Q x K(half)^T  (ldmatrix-fed) ----
        float s[2][4][4];
        #pragma unroll
        for (int rt = 0; rt < 2; ++rt)
            #pragma unroll
            for (int j = 0; j < 4; ++j)
                { s[rt][j][0] = s[rt][j][1] = s[rt][j][2] = s[rt][j][3] = 0.f; }

        #pragma unroll 4
        for (int kk = 0; kk < 16; ++kk) {
            uint32_t A0[4], A1[4], B0[4], B1[4];
            ldsm_x4(A0, qb0 + kk * 32u);
            ldsm_x4(A1, qb1 + kk * 32u);
            ldsm_x4(B0, kb0 + kk * 32u);   // {b0(j0), b1(j0), b0(j1), b1(j1)}
            ldsm_x4(B1, kb1 + kk * 32u);   // {b0(j2), b1(j2), b0(j3), b1(j3)}
            mma_tf32(s[0][0], A0, B0[0], B0[1]);
            mma_tf32(s[0][1], A0, B0[2], B0[3]);
            mma_tf32(s[0][2], A0, B1[0], B1[1]);
            mma_tf32(s[0][3], A0, B1[2], B1[3]);
            mma_tf32(s[1][0], A1, B0[0], B0[1]);
            mma_tf32(s[1][1], A1, B0[2], B0[3]);
            mma_tf32(s[1][2], A1, B1[0], B1[1]);
            mma_tf32(s[1][3], A1, B1[2], B1[3]);
        }

        // ---- warp-local softmax (log2 domain) ----
        const bool diag = (jt >= 2 * it);
        #pragma unroll
        for (int rt = 0; rt < 2; ++rt) {
            const int r0 = q0 + 32 * rg + 16 * rt + g, r1 = r0 + 8;
            float t0 = -1e30f, t1 = -1e30f;
            #pragma unroll
            for (int j = 0; j < 4; ++j) {
                #pragma unroll
                for (int c = 0; c < 4; ++c) s[rt][j][c] *= kScaleLog2;
                if (diag) {
                    int col = k0 + 32 * half + 8 * j + 2 * lq;
                    if (col     > r0) s[rt][j][0] = -1e30f;
                    if (col + 1 > r0) s[rt][j][1] = -1e30f;
                    if (col     > r1) s[rt][j][2] = -1e30f;
                    if (col + 1 > r1) s[rt][j][3] = -1e30f;
                }
                t0 = fmaxf(t0, fmaxf(s[rt][j][0], s[rt][j][1]));
                t1 = fmaxf(t1, fmaxf(s[rt][j][2], s[rt][j][3]));
            }
            t0 = fmaxf(t0, __shfl_xor_sync(0xffffffffu, t0, 1));
            t0 = fmaxf(t0, __shfl_xor_sync(0xffffffffu, t0, 2));
            t1 = fmaxf(t1, __shfl_xor_sync(0xffffffffu, t1, 1));
            t1 = fmaxf(t1, __shfl_xor_sync(0xffffffffu, t1, 2));

            const float mn0 = fmaxf(mm[2 * rt], t0), mn1 = fmaxf(mm[2 * rt + 1], t1);
            const float al0 = fast_ex2(mm[2 * rt] - mn0), al1 = fast_ex2(mm[2 * rt + 1] - mn1);
            // all-masked guard: half-row that has seen no unmasked key -> p = 0
            const float v0 = (mn0 > -9.0e29f) ? 1.f : 0.f;
            const float v1 = (mn1 > -9.0e29f) ? 1.f : 0.f;
            mm[2 * rt] = mn0; mm[2 * rt + 1] = mn1;

            float rs0 = 0.f, rs1 = 0.f;
            #pragma unroll
            for (int j = 0; j < 4; ++j) {
                float p0 = to_tf32(fast_ex2(s[rt][j][0] - mn0)) * v0;
                float p1 = to_tf32(fast_ex2(s[rt][j][1] - mn0)) * v0;
                float p2 = to_tf32(fast_ex2(s[rt][j][2] - mn1)) * v1;
                float p3 = to_tf32(fast_ex2(s[rt][j][3] - mn1)) * v1;
                rs0 += p0 + p1;
                rs1 += p2 + p3;
                float2 w0; w0.x = p0; w0.y = p1;
                float2 w1; w1.x = p2; w1.y = p3;
                *reinterpret_cast<float2*>(&Pw[(16 * rt + g) * PSTR + 8 * j + 2 * lq])     = w0;
                *reinterpret_cast<float2*>(&Pw[(16 * rt + g + 8) * PSTR + 8 * j + 2 * lq]) = w1;
            }
            rs0 += __shfl_xor_sync(0xffffffffu, rs0, 1);
            rs0 += __shfl_xor_sync(0xffffffffu, rs0, 2);
            rs1 += __shfl_xor_sync(0xffffffffu, rs1, 1);
            rs1 += __shfl_xor_sync(0xffffffffu, rs1, 2);
            ll[2 * rt]     = ll[2 * rt] * al0 + rs0;
            ll[2 * rt + 1] = ll[2 * rt + 1] * al1 + rs1;
            #pragma unroll
            for (int jn = 0; jn < 16; ++jn) {
                o[rt][jn][0] *= al0; o[rt][jn][1] *= al0;
                o[rt][jn][2] *= al1; o[rt][jn][3] *= al1;
            }
        }
        __syncwarp();   // P visible within the warp

        // ---- V(jt) resident ----
        if (havek) asm volatile("cp.async.wait_group 1;" ::: "memory");
        else       asm volatile("cp.async.wait_group 0;" ::: "memory");
        __syncthreads();

        // ---- GEMM2: O[32 x 128] += P(32x32) x V(half keys) ----
        #pragma unroll
        for (int kk = 0; kk < 4; ++kk) {
            uint32_t PA0[4], PA1[4];
            ldsm_x4(PA0, pb0 + kk * 32u);
            ldsm_x4(PA1, pb1 + kk * 32u);
            #pragma unroll
            for (int jn = 0; jn < 16; ++jn) {
                const float* vp = &Vs[(32 * half + 8 * kk + lq) * VSTR + 8 * jn + g];
                uint32_t b0 = __float_as_uint(vp[0]);
                uint32_t b1 = __float_as_uint(vp[4 * VSTR]);
                mma_tf32(o[0][jn], PA0, b0, b1);
                mma_tf32(o[1][jn], PA1, b0, b1);
            }
        }
    }

    // ================= final merge of the two key-halves =================
    if (lq == 0) {
        #pragma unroll
        for (int i = 0; i < 4; ++i) {
            int rloc = 32 * rg + 16 * (i >> 1) + g + 8 * (i & 1);
            sm[OFF_ML + half * 256 + 2 * rloc]     = mm[i];
            sm[OFF_ML + half * 256 + 2 * rloc + 1] = ll[i];
        }
    }
    __syncthreads();
    float coef[4];
    #pragma unroll
    for (int i = 0; i < 4; ++i) {
        int rloc = 32 * rg + 16 * (i >> 1) + g + 8 * (i & 1);
        float mo = sm[OFF_ML + (1 - half) * 256 + 2 * rloc];
        float lo = sm[OFF_ML + (1 - half) * 256 + 2 * rloc + 1];
        float ms = fmaxf(mm[i], mo);
        float lt = ll[i] * fast_ex2(mm[i] - ms) + lo * fast_ex2(mo - ms);
        coef[i] = fast_ex2(mm[i] - ms) / lt;
    }
    __syncthreads();

    if (half == 0) {
        #pragma unroll
        for (int rt = 0; rt < 2; ++rt)
            #pragma unroll
            for (int jn = 0; jn < 16; ++jn) {
                int d = 8 * jn + 2 * lq;
                int r0 = 32 * rg + 16 * rt + g;
                sm[OFF_MRG + r0 * 132 + d]           = o[rt][jn][0] * coef[2 * rt];
                sm[OFF_MRG + r0 * 132 + d + 1]       = o[rt][jn][1] * coef[2 * rt];
                sm[OFF_MRG + (r0 + 8) * 132 + d]     = o[rt][jn][2] * coef[2 * rt + 1];
                sm[OFF_MRG + (r0 + 8) * 132 + d + 1] = o[rt][jn][3] * coef[2 * rt + 1];
            }
    }
    __syncthreads();
    if (half == 1) {
        #pragma unroll
        for (int rt = 0; rt < 2; ++rt)
            #pragma unroll
            for (int jn = 0; jn < 16; ++jn) {
                int d = 8 * jn + 2 * lq;
                int r0 = 32 * rg + 16 * rt + g;
                float2 w0, w1;
                w0.x = sm[OFF_MRG + r0 * 132 + d]           + o[rt][jn][0] * coef[2 * rt];
                w0.y = sm[OFF_MRG + r0 * 132 + d + 1]       + o[rt][jn][1] * coef[2 * rt];
                w1.x = sm[OFF_MRG + (r0 + 8) * 132 + d]     + o[rt][jn][2] * coef[2 * rt + 1];
                w1.y = sm[OFF_MRG + (r0 + 8) * 132 + d + 1] + o[rt][jn][3] * coef[2 * rt + 1];
                *reinterpret_cast<float2*>(&gout[base + (size_t)(q0 + r0) * kD + d])     = w0;
                *reinterpret_cast<float2*>(&gout[base + (size_t)(q0 + r0 + 8) * kD + d]) = w1;
            }
    }
}

extern "C" void kernel_launch(void* const* d_in, const int* in_sizes, int n_in,
                              void* d_out, int out_size) {
    (void)in_sizes; (void)n_in; (void)out_size;
    const float* q = (const float*)d_in[0];
    const float* k = (const float*)d_in[1];
    const float* v = (const float*)d_in[2];
    float* out = (float*)d_out;

    const size_t smem = (size_t)SMEM_FLOATS * sizeof(float);   // 208896 B
    cudaFuncSetAttribute(fa_tf32_ldsm_kernel,
                         cudaFuncAttributeMaxDynamicSharedMemorySize, (int)smem);

    dim3 grid(kL / BR, 32);   // 16 q-tiles x (B*H = 32)
    fa_tf32_ldsm_kernel<<<grid, NTHR, smem>>>(q, k, v, out);
}

// round 11
// speedup vs baseline: 2.1090x; 1.7052x over previous
#include <cuda_runtime.h>
#include <cuda_fp16.h>
#include <cstdint>

// Causal prefill attention, q,k,v,out: [B,H,L,D] fp32. B=2 H=16 L=2048 D=128.
// Two kernels: (1) convert q/k/v fp32 -> fp16 (RN) into static device buffers,
// (2) flash-attention-2 with fp16 mma.sync.m16n8k16 (fp32 accum).
// BR=128, BC=64, 8 warps; warp (rg, half) = 32 query rows x 32-key half with
// per-warp online softmax and one O/l/m merge at the end.
// K and V double-buffered via cp.async (pure fp16, no hot-path conversion);
// all MMA operands ldmatrix-fed (V via ldmatrix.x4.trans). 1 barrier/iter.

namespace {
constexpr int kL = 2048, kD = 128, kBH = 32;
constexpr int BR = 128, BC = 64, NTHR = 256;
constexpr int kN = kBH * kL * kD;                 // 8388608 elements per tensor
constexpr float kScaleLog2 = 0.12751745210670913f;  // (1/sqrt(128))*log2(e)

// fp16 smem strides (in halves) and byte offsets
constexpr int TSTR = 136;   // Q/K/V row stride: 272 B == 16 mod 128 -> ldsm conflict-free
constexpr int PSTR = 40;    // P row stride: 80 B -> 8 distinct 16B groups
constexpr int B_Q  = 0;                           // 128*272 = 34816
constexpr int B_K0 = 34816;                       // 64*272 = 17408 each
constexpr int B_K1 = 52224;
constexpr int B_V0 = 69632;
constexpr int B_V1 = 87040;
constexpr int B_P  = 104448;                      // 8 warps x 32*80 = 20480
constexpr int B_ML = 124928;                      // 512 f32 = 2048
constexpr int SMEM_BYTES = 126976;
constexpr int B_MRG = B_K0;                       // epilogue merge: 128x132 f32 = 67584 B
}

__device__ __half g_q16[kN];
__device__ __half g_k16[kN];
__device__ __half g_v16[kN];

__global__ void convert_f32_to_f16(const float* __restrict__ q,
                                   const float* __restrict__ k,
                                   const float* __restrict__ v) {
    const int n4 = kN / 4;
    for (int t = blockIdx.x * blockDim.x + threadIdx.x; t < 3 * n4;
         t += gridDim.x * blockDim.x) {
        int which = t / n4, i = t - which * n4;
        const float4* src = (const float4*)(which == 0 ? q : (which == 1 ? k : v));
        __half* dst = (which == 0 ? g_q16 : (which == 1 ? g_k16 : g_v16));
        float4 s = src[i];
        __half2 lo = __floats2half2_rn(s.x, s.y);
        __half2 hi = __floats2half2_rn(s.z, s.w);
        uint2 w;
        w.x = *reinterpret_cast<uint32_t*>(&lo);
        w.y = *reinterpret_cast<uint32_t*>(&hi);
        reinterpret_cast<uint2*>(dst)[i] = w;
    }
}

__device__ __forceinline__ float fast_ex2(float x) {
    float y;
    asm("ex2.approx.f32 %0, %1;" : "=f"(y) : "f"(x));
    return y;
}
__device__ __forceinline__ uint32_t smem_u32(const void* p) {
    uint32_t a;
    asm("{ .reg .u64 t; cvta.to.shared.u64 t, %1; cvt.u32.u64 %0, t; }" : "=r"(a) : "l"(p));
    return a;
}
__device__ __forceinline__ void ldsm_x4(uint32_t r[4], uint32_t addr) {
    asm volatile("ldmatrix.sync.aligned.m8n8.x4.shared.b16 {%0,%1,%2,%3}, [%4];"
                 : "=r"(r[0]), "=r"(r[1]), "=r"(r[2]), "=r"(r[3]) : "r"(addr));
}
__device__ __forceinline__ void ldsm_x4_t(uint32_t r[4], uint32_t addr) {
    asm volatile("ldmatrix.sync.aligned.m8n8.x4.trans.shared.b16 {%0,%1,%2,%3}, [%4];"
                 : "=r"(r[0]), "=r"(r[1]), "=r"(r[2]), "=r"(r[3]) : "r"(addr));
}
__device__ __forceinline__ void mma_f16(float c[4], const uint32_t a[4],
                                        uint32_t b0, uint32_t b1) {
    asm volatile(
        "mma.sync.aligned.m16n8k16.row.col.f32.f16.f16.f32 "
        "{%0,%1,%2,%3}, {%4,%5,%6,%7}, {%8,%9}, {%0,%1,%2,%3};\n"
        : "+f"(c[0]), "+f"(c[1]), "+f"(c[2]), "+f"(c[3])
        : "r"(a[0]), "r"(a[1]), "r"(a[2]), "r"(a[3]), "r"(b0), "r"(b1));
}

// async-stage one 64x128 fp16 tile (16B copies)
__device__ __forceinline__ void stage_tile16(uint32_t dst, const __half* __restrict__ src,
                                             int k0, int tid) {
    #pragma unroll
    for (int i = 0; i < 4; ++i) {
        int lin = tid + i * NTHR;
        int r = lin >> 4, c = lin & 15;
        const __half* p = src + (size_t)(k0 + r) * kD + c * 8;
        uint32_t d = dst + (uint32_t)(r * (TSTR * 2) + c * 16);
        asm volatile("cp.async.ca.shared.global [%0], [%1], 16;" :: "r"(d), "l"(p));
    }
}

__global__ __launch_bounds__(NTHR, 1)
void fa_f16_kernel(float* __restrict__ gout) {
    extern __shared__ char smem[];
    const uint32_t sb = smem_u32(smem);
    float* MLp = reinterpret_cast<float*>(smem + B_ML);
    float* MRG = reinterpret_cast<float*>(smem + B_MRG);

    const int tid  = threadIdx.x;
    const int lane = tid & 31;
    const int wid  = tid >> 5;           // 0..7
    const int rg   = wid >> 1;           // row-group 0..3 (32 rows each)
    const int half = wid & 1;            // key half within each BC tile
    const int g    = lane >> 2;
    const int lq   = lane & 3;
    const int l15  = lane & 15;

    // ---- ldmatrix base addresses (bytes) ----
    const int chi = (lane >> 4) & 1;     // A-pattern 16B column selector
    const uint32_t qA0 = sb + B_Q + (uint32_t)((32 * rg + l15) * (TSTR * 2) + chi * 16);
    const uint32_t qA1 = qA0 + (uint32_t)(16 * TSTR * 2);
    const uint32_t pW  = sb + B_P + (uint32_t)(wid * 32 * PSTR * 2);
    const uint32_t pA0 = pW + (uint32_t)(l15 * (PSTR * 2) + chi * 16);
    const uint32_t pA1 = pA0 + (uint32_t)(16 * PSTR * 2);
    // K B-pattern: keyrow = 32*half + (lane>>4)*8 + (lane&7); col 16B = (lane>>3)&1
    const uint32_t krel = (uint32_t)((32 * half + ((lane >> 4) << 3) + (lane & 7)) * (TSTR * 2)
                                     + ((lane >> 3) & 1) * 16);
    // V trans-pattern: keyrow = 32*half + (lane&15); d 16B-block = (lane>>4)
    const uint32_t vrel = (uint32_t)((32 * half + l15) * (TSTR * 2) + ((lane >> 4) & 1) * 16);

    const int it = (int)gridDim.x - 1 - (int)blockIdx.x;   // heavy tiles first
    const int bh = blockIdx.y;
    const size_t base = (size_t)bh * kL * kD;
    const int q0 = it * BR;
    const __half* gq = g_q16 + base;
    const __half* gk = g_k16 + base;
    const __half* gv = g_v16 + base;
    __half* Ph = reinterpret_cast<__half*>(smem + B_P) + wid * 32 * PSTR;

    // ---- prologue: async-stage Q + K(0) + V(0) as group 0 ----
    #pragma unroll
    for (int i = 0; i < 8; ++i) {       // Q: 128x128 fp16
        int lin = tid + i * NTHR;
        int r = lin >> 4, c = lin & 15;
        const __half* p = gq + (size_t)(q0 + r) * kD + c * 8;
        uint32_t d = sb + B_Q + (uint32_t)(r * (TSTR * 2) + c * 16);
        asm volatile("cp.async.ca.shared.global [%0], [%1], 16;" :: "r"(d), "l"(p));
    }
    stage_tile16(sb + B_K0, gk, 0, tid);
    stage_tile16(sb + B_V0, gv, 0, tid);
    asm volatile("cp.async.commit_group;" ::: "memory");

    float o[2][16][4];
    #pragma unroll
    for (int rt = 0; rt < 2; ++rt)
        #pragma unroll
        for (int jn = 0; jn < 16; ++jn)
            { o[rt][jn][0] = o[rt][jn][1] = o[rt][jn][2] = o[rt][jn][3] = 0.f; }
    float mm[4] = {-1e30f, -1e30f, -1e30f, -1e30f};
    float ll[4] = {0.f, 0.f, 0.f, 0.f};

    const int njt = 2 * it + 2;
    for (int jt = 0; jt < njt; ++jt) {
        const int k0 = jt * BC;

        asm volatile("cp.async.wait_group 0;" ::: "memory");   // K(jt),V(jt) resident
        __syncthreads();   // visible to all; all warps done with buffers (jt-1)

        // stage K/V(jt+1) into the other buffers (their prior readers passed the barrier)
        if (jt + 1 < njt) {
            stage_tile16(sb + ((jt & 1) ? B_K0 : B_K1), gk, k0 + BC, tid);
            stage_tile16(sb + ((jt & 1) ? B_V0 : B_V1), gv, k0 + BC, tid);
            asm volatile("cp.async.commit_group;" ::: "memory");
        }

        const uint32_t kB = sb + (uint32_t)((jt & 1) ? B_K1 : B_K0) + krel;
        const uint32_t vB = sb + (uint32_t)((jt & 1) ? B_V1 : B_V0) + vrel;

        // ---- GEMM1: S[32 x 32] = Q x K(half)^T, k16 steps ----
        float s[2][4][4];
        #pragma unroll
        for (int rt = 0; rt < 2; ++rt)
            #pragma unroll
            for (int j = 0; j < 4; ++j)
                { s[rt][j][0] = s[rt][j][1] = s[rt][j][2] = s[rt][j][3] = 0.f; }

        #pragma unroll
        for (int kk = 0; kk < 8; ++kk) {   // 8 x k16 = 128 d
            uint32_t A0[4], A1[4], B0[4], B1[4];
            ldsm_x4(A0, qA0 + kk * 32u);
            ldsm_x4(A1, qA1 + kk * 32u);
            ldsm_x4(B0, kB + kk * 32u);                         // jn0, jn1
            ldsm_x4(B1, kB + 16u * (TSTR * 2) + kk * 32u);      // jn2, jn3
            mma_f16(s[0][0], A0, B0[0], B0[1]);
            mma_f16(s[0][1], A0, B0[2], B0[3]);
            mma_f16(s[0][2], A0, B1[0], B1[1]);
            mma_f16(s[0][3], A0, B1[2], B1[3]);
            mma_f16(s[1][0], A1, B0[0], B0[1]);
            mma_f16(s[1][1], A1, B0[2], B0[3]);
            mma_f16(s[1][2], A1, B1[0], B1[1]);
            mma_f16(s[1][3], A1, B1[2], B1[3]);
        }

        // ---- warp-local softmax (log2 domain) ----
        const bool diag = (jt >= 2 * it);
        #pragma unroll
        for (int rt = 0; rt < 2; ++rt) {
            const int r0 = q0 + 32 * rg + 16 * rt + g, r1 = r0 + 8;
            float t0 = -1e30f, t1 = -1e30f;
            #pragma unroll
            for (int j = 0; j < 4; ++j) {
                #pragma unroll
                for (int c = 0; c < 4; ++c) s[rt][j][c] *= kScaleLog2;
                if (diag) {
                    int col = k0 + 32 * half + 8 * j + 2 * lq;
                    if (col     > r0) s[rt][j][0] = -1e30f;
                    if (col + 1 > r0) s[rt][j][1] = -1e30f;
                    if (col     > r1) s[rt][j][2] = -1e30f;
                    if (col + 1 > r1) s[rt][j][3] = -1e30f;
                }
                t0 = fmaxf(t0, fmaxf(s[rt][j][0], s[rt][j][1]));
                t1 = fmaxf(t1, fmaxf(s[rt][j][2], s[rt][j][3]));
            }
            t0 = fmaxf(t0, __shfl_xor_sync(0xffffffffu, t0, 1));
            t0 = fmaxf(t0, __shfl_xor_sync(0xffffffffu, t0, 2));
            t1 = fmaxf(t1, __shfl_xor_sync(0xffffffffu, t1, 1));
            t1 = fmaxf(t1, __shfl_xor_sync(0xffffffffu, t1, 2));

            const float mn0 = fmaxf(mm[2 * rt], t0), mn1 = fmaxf(mm[2 * rt + 1], t1);
            const float al0 = fast_ex2(mm[2 * rt] - mn0), al1 = fast_ex2(mm[2 * rt + 1] - mn1);
            // all-masked half-row guard
            const float v0 = (mn0 > -9.0e29f) ? 1.f : 0.f;
            const float v1 = (mn1 > -9.0e29f) ? 1.f : 0.f;
            mm[2 * rt] = mn0; mm[2 * rt + 1] = mn1;

            float rs0 = 0.f, rs1 = 0.f;
            #pragma unroll
            for (int j = 0; j < 4; ++j) {
                float p0 = fast_ex2(s[rt][j][0] - mn0) * v0;
                float p1 = fast_ex2(s[rt][j][1] - mn0) * v0;
                float p2 = fast_ex2(s[rt][j][2] - mn1) * v1;
                float p3 = fast_ex2(s[rt][j][3] - mn1) * v1;
                __half2 h0 = __floats2half2_rn(p0, p1);
                __half2 h1 = __floats2half2_rn(p2, p3);
                rs0 += __low2float(h0) + __high2float(h0);   // sum what GEMM2 will see
                rs1 += __low2float(h1) + __high2float(h1);
                *reinterpret_cast<__half2*>(&Ph[(16 * rt + g) * PSTR + 8 * j + 2 * lq])     = h0;
                *reinterpret_cast<__half2*>(&Ph[(16 * rt + g + 8) * PSTR + 8 * j + 2 * lq]) = h1;
            }
            rs0 += __shfl_xor_sync(0xffffffffu, rs0, 1);
            rs0 += __shfl_xor_sync(0xffffffffu, rs0, 2);
            rs1 += __shfl_xor_sync(0xffffffffu, rs1, 1);
            rs1 += __shfl_xor_sync(0xffffffffu, rs1, 2);
            ll[2 * rt]     = ll[2 * rt] * al0 + rs0;
            ll[2 * rt + 1] = ll[2 * rt + 1] * al1 + rs1;
            #pragma unroll
            for (int jn = 0; jn < 16; ++jn) {
                o[rt][jn][0] *= al0; o[rt][jn][1] *= al0;
                o[rt][jn][2] *= al1; o[rt][jn][3] *= al1;
            }
        }
        __syncwarp();   // P visible within the warp

        // ---- GEMM2: O[32 x 128] += P(32x32) x V(half keys); V via ldsm trans ----
        #pragma unroll
        for (int kk = 0; kk < 2; ++kk) {   // 2 x k16 = 32 keys
            uint32_t PA0[4], PA1[4];
            ldsm_x4(PA0, pA0 + kk * 32u);
            ldsm_x4(PA1, pA1 + kk * 32u);
            const uint32_t vkk = vB + (uint32_t)(kk * 16 * (TSTR * 2));
            #pragma unroll
            for (int jp = 0; jp < 8; ++jp) {   // each covers 2 jn (16 d cols)
                uint32_t VB[4];
                ldsm_x4_t(VB, vkk + jp * 32u);
                mma_f16(o[0][2 * jp],     PA0, VB[0], VB[1]);
                mma_f16(o[0][2 * jp + 1], PA0, VB[2], VB[3]);
                mma_f16(o[1][2 * jp],     PA1, VB[0], VB[1]);
                mma_f16(o[1][2 * jp + 1], PA1, VB[2], VB[3]);
            }
        }
    }

    // ================= final merge of the two key-halves =================
    if (lq == 0) {
        #pragma unroll
        for (int i = 0; i < 4; ++i) {
            int rloc = 32 * rg + 16 * (i >> 1) + g + 8 * (i & 1);
            MLp[half * 256 + 2 * rloc]     = mm[i];
            MLp[half * 256 + 2 * rloc + 1] = ll[i];
        }
    }
    __syncthreads();
    float coef[4];
    #pragma unroll
    for (int i = 0; i < 4; ++i) {
        int rloc = 32 * rg + 16 * (i >> 1) + g + 8 * (i & 1);
        float mo = MLp[(1 - half) * 256 + 2 * rloc];
        float lo = MLp[(1 - half) * 256 + 2 * rloc + 1];
        float ms = fmaxf(mm[i], mo);
        float lt = ll[i] * fast_ex2(mm[i] - ms) + lo * fast_ex2(mo - ms);
        coef[i] = fast_ex2(mm[i] - ms) / lt;
    }
    __syncthreads();

    if (half == 0) {
        #pragma unroll
        for (int rt = 0; rt < 2; ++rt)
            #pragma unroll
            for (int jn = 0; jn < 16; ++jn) {
                int d = 8 * jn + 2 * lq;
                int r0 = 32 * rg + 16 * rt + g;
                MRG[r0 * 132 + d]           = o[rt][jn][0] * coef[2 * rt];
                MRG[r0 * 132 + d + 1]       = o[rt][jn][1] * coef[2 * rt];
                MRG[(r0 + 8) * 132 + d]     = o[rt][jn][2] * coef[2 * rt + 1];
                MRG[(r0 + 8) * 132 + d + 1] = o[rt][jn][3] * coef[2 * rt + 1];
            }
    }
    __syncthreads();
    if (half == 1) {
        const size_t gbase = (size_t)bh * kL * kD;
        #pragma unroll
        for (int rt = 0; rt < 2; ++rt)
            #pragma unroll
            for (int jn = 0; jn < 16; ++jn) {
                int d = 8 * jn + 2 * lq;
                int r0 = 32 * rg + 16 * rt + g;
                float2 w0, w1;
                w0.x = MRG[r0 * 132 + d]           + o[rt][jn][0] * coef[2 * rt];
                w0.y = MRG[r0 * 132 + d + 1]       + o[rt][jn][1] * coef[2 * rt];
                w1.x = MRG[(r0 + 8) * 132 + d]     + o[rt][jn][2] * coef[2 * rt + 1];
                w1.y = MRG[(r0 + 8) * 132 + d + 1] + o[rt][jn][3] * coef[2 * rt + 1];
                *reinterpret_cast<float2*>(&gout[gbase + (size_t)(q0 + r0) * kD + d])     = w0;
                *reinterpret_cast<float2*>(&gout[gbase + (size_t)(q0 + r0 + 8) * kD + d]) = w1;
            }
    }
}

extern "C" void kernel_launch(void* const* d_in, const int* in_sizes, int n_in,
                              void* d_out, int out_size) {
    (void)in_sizes; (void)n_in; (void)out_size;
    const float* q = (const float*)d_in[0];
    const float* k = (const float*)d_in[1];
    const float* v = (const float*)d_in[2];
    float* out = (float*)d_out;

    convert_f32_to_f16<<<2048, 256>>>(q, k, v);

    cudaFuncSetAttribute(fa_f16_kernel,
                         cudaFuncAttributeMaxDynamicSharedMemorySize, SMEM_BYTES);
    dim3 grid(kL / BR, kBH);   // 16 q-tiles x 32 heads
    fa_f16_kernel<<<grid, NTHR, SMEM_BYTES>>>(out);
}

// round 12
// speedup vs baseline: 2.1515x; 1.0201x over previous
#include <cuda_runtime.h>
#include <cuda_fp16.h>
#include <cstdint>

// Causal prefill attention, q,k,v,out: [B,H,L,D] fp32. B=2 H=16 L=2048 D=128.
// Kernel 1: convert k/v fp32 -> fp16 (RN) into static device buffers.
// Kernel 2: flash-attention-2, fp16 mma.sync.m16n8k16 (fp32 accum).
//   Q converted + pre-scaled by log2(e)/sqrt(D) inline (read once per CTA),
//   so S comes out of GEMM1 already in log2 domain (no per-iter scale muls).
//   O-rescale skipped via warp vote when the running max is unchanged.
//   m initialized to -60 so fully-masked half-rows give p = ex2(-huge) = 0
//   naturally (no guard flags).
// BR=128, BC=64, 8 warps; warp (rg, half) = 32 query rows x 32-key half,
// per-warp online softmax, one O/l/m merge at the end.
// K and V double-buffered via cp.async; all MMA operands ldmatrix-fed.

namespace {
constexpr int kL = 2048, kD = 128, kBH = 32;
constexpr int BR = 128, BC = 64, NTHR = 256;
constexpr int kN = kBH * kL * kD;
constexpr float kScaleLog2 = 0.12751745210670913f;  // (1/sqrt(128))*log2(e)
constexpr float kMInit = -60.0f;   // scores in log2 domain are |s| < ~40

// fp16 smem strides (halves) and byte offsets
constexpr int TSTR = 136;   // 272 B == 16 mod 128 -> ldsm conflict-free
constexpr int PSTR = 40;    // 80 B -> 8 distinct 16B groups
constexpr int B_Q  = 0;                           // 128*272 = 34816
constexpr int B_K0 = 34816;
constexpr int B_K1 = 52224;
constexpr int B_V0 = 69632;
constexpr int B_V1 = 87040;
constexpr int B_P  = 104448;                      // 8 x 32*80 = 20480
constexpr int B_ML = 124928;                      // 512 f32
constexpr int SMEM_BYTES = 126976;
constexpr int B_MRG = B_K0;                       // epilogue merge buffer
}

__device__ __half g_k16[kN];
__device__ __half g_v16[kN];

__global__ void convert_kv_f16(const float* __restrict__ k,
                               const float* __restrict__ v) {
    const int n4 = kN / 4;
    for (int t = blockIdx.x * blockDim.x + threadIdx.x; t < 2 * n4;
         t += gridDim.x * blockDim.x) {
        int which = t / n4, i = t - which * n4;
        const float4* src = (const float4*)(which == 0 ? k : v);
        __half* dst = (which == 0 ? g_k16 : g_v16);
        float4 s = src[i];
        __half2 lo = __floats2half2_rn(s.x, s.y);
        __half2 hi = __floats2half2_rn(s.z, s.w);
        uint2 w;
        w.x = *reinterpret_cast<uint32_t*>(&lo);
        w.y = *reinterpret_cast<uint32_t*>(&hi);
        reinterpret_cast<uint2*>(dst)[i] = w;
    }
}

__device__ __forceinline__ float fast_ex2(float x) {
    float y;
    asm("ex2.approx.f32 %0, %1;" : "=f"(y) : "f"(x));
    return y;
}
__device__ __forceinline__ uint32_t smem_u32(const void* p) {
    uint32_t a;
    asm("{ .reg .u64 t; cvta.to.shared.u64 t, %1; cvt.u32.u64 %0, t; }" : "=r"(a) : "l"(p));
    return a;
}
__device__ __forceinline__ void ldsm_x4(uint32_t r[4], uint32_t addr) {
    asm volatile("ldmatrix.sync.aligned.m8n8.x4.shared.b16 {%0,%1,%2,%3}, [%4];"
                 : "=r"(r[0]), "=r"(r[1]), "=r"(r[2]), "=r"(r[3]) : "r"(addr));
}
__device__ __forceinline__ void ldsm_x4_t(uint32_t r[4], uint32_t addr) {
    asm volatile("ldmatrix.sync.aligned.m8n8.x4.trans.shared.b16 {%0,%1,%2,%3}, [%4];"
                 : "=r"(r[0]), "=r"(r[1]), "=r"(r[2]), "=r"(r[3]) : "r"(addr));
}
__device__ __forceinline__ void mma_f16(float c[4], const uint32_t a[4],
                                        uint32_t b0, uint32_t b1) {
    asm volatile(
        "mma.sync.aligned.m16n8k16.row.col.f32.f16.f16.f32 "
        "{%0,%1,%2,%3}, {%4,%5,%6,%7}, {%8,%9}, {%0,%1,%2,%3};\n"
        : "+f"(c[0]), "+f"(c[1]), "+f"(c[2]), "+f"(c[3])
        : "r"(a[0]), "r"(a[1]), "r"(a[2]), "r"(a[3]), "r"(b0), "r"(b1));
}

// async-stage one 64x128 fp16 tile (16B copies)
__device__ __forceinline__ void stage_tile16(uint32_t dst, const __half* __restrict__ src,
                                             int k0, int tid) {
    #pragma unroll
    for (int i = 0; i < 4; ++i) {
        int lin = tid + i * NTHR;
        int r = lin >> 4, c = lin & 15;
        const __half* p = src + (size_t)(k0 + r) * kD + c * 8;
        uint32_t d = dst + (uint32_t)(r * (TSTR * 2) + c * 16);
        asm volatile("cp.async.ca.shared.global [%0], [%1], 16;" :: "r"(d), "l"(p));
    }
}

__global__ __launch_bounds__(NTHR, 1)
void fa_f16_kernel(const float* __restrict__ gqf, float* __restrict__ gout) {
    extern __shared__ char smem[];
    const uint32_t sb = smem_u32(smem);
    float* MLp = reinterpret_cast<float*>(smem + B_ML);
    float* MRG = reinterpret_cast<float*>(smem + B_MRG);

    const int tid  = threadIdx.x;
    const int lane = tid & 31;
    const int wid  = tid >> 5;
    const int rg   = wid >> 1;           // row-group 0..3 (32 rows each)
    const int half = wid & 1;            // key half within each BC tile
    const int g    = lane >> 2;
    const int lq   = lane & 3;
    const int l15  = lane & 15;

    // ---- ldmatrix base addresses (bytes) ----
    const int chi = (lane >> 4) & 1;
    const uint32_t qA0 = sb + B_Q + (uint32_t)((32 * rg + l15) * (TSTR * 2) + chi * 16);
    const uint32_t qA1 = qA0 + (uint32_t)(16 * TSTR * 2);
    const uint32_t pW  = sb + B_P + (uint32_t)(wid * 32 * PSTR * 2);
    const uint32_t pA0 = pW + (uint32_t)(l15 * (PSTR * 2) + chi * 16);
    const uint32_t pA1 = pA0 + (uint32_t)(16 * PSTR * 2);
    const uint32_t krel = (uint32_t)((32 * half + ((lane >> 4) << 3) + (lane & 7)) * (TSTR * 2)
                                     + ((lane >> 3) & 1) * 16);
    const uint32_t vrel = (uint32_t)((32 * half + l15) * (TSTR * 2) + ((lane >> 4) & 1) * 16);

    const int it = (int)gridDim.x - 1 - (int)blockIdx.x;   // heavy tiles first
    const int bh = blockIdx.y;
    const size_t base = (size_t)bh * kL * kD;
    const int q0 = it * BR;
    const __half* gk = g_k16 + base;
    const __half* gv = g_v16 + base;
    __half* Ph = reinterpret_cast<__half*>(smem + B_P) + wid * 32 * PSTR;

    // ---- prologue: stage K(0)/V(0) async; convert+prescale Q inline ----
    stage_tile16(sb + B_K0, gk, 0, tid);
    stage_tile16(sb + B_V0, gv, 0, tid);
    asm volatile("cp.async.commit_group;" ::: "memory");

    {
        __half* Qh = reinterpret_cast<__half*>(smem + B_Q);
        const float* qsrc = gqf + base;
        #pragma unroll
        for (int i = 0; i < 16; ++i) {       // 128x128 f32 -> fp16 (prescaled)
            int lin = tid + i * NTHR;
            int r = lin >> 5, c4 = (lin & 31) << 2;
            float4 t = *reinterpret_cast<const float4*>(&qsrc[(size_t)(q0 + r) * kD + c4]);
            __half2 h0 = __floats2half2_rn(t.x * kScaleLog2, t.y * kScaleLog2);
            __half2 h1 = __floats2half2_rn(t.z * kScaleLog2, t.w * kScaleLog2);
            uint2 w;
            w.x = *reinterpret_cast<uint32_t*>(&h0);
            w.y = *reinterpret_cast<uint32_t*>(&h1);
            *reinterpret_cast<uint2*>(&Qh[r * TSTR + c4]) = w;
        }
    }

    float o[2][16][4];
    #pragma unroll
    for (int rt = 0; rt < 2; ++rt)
        #pragma unroll
        for (int jn = 0; jn < 16; ++jn)
            { o[rt][jn][0] = o[rt][jn][1] = o[rt][jn][2] = o[rt][jn][3] = 0.f; }
    float mm[4] = {kMInit, kMInit, kMInit, kMInit};
    float ll[4] = {0.f, 0.f, 0.f, 0.f};

    const int njt = 2 * it + 2;
    for (int jt = 0; jt < njt; ++jt) {
        const int k0 = jt * BC;

        asm volatile("cp.async.wait_group 0;" ::: "memory");   // K(jt),V(jt) resident
        __syncthreads();   // also covers Q visibility on jt==0

        if (jt + 1 < njt) {
            stage_tile16(sb + ((jt & 1) ? B_K0 : B_K1), gk, k0 + BC, tid);
            stage_tile16(sb + ((jt & 1) ? B_V0 : B_V1), gv, k0 + BC, tid);
            asm volatile("cp.async.commit_group;" ::: "memory");
        }

        const uint32_t kB = sb + (uint32_t)((jt & 1) ? B_K1 : B_K0) + krel;
        const uint32_t vB = sb + (uint32_t)((jt & 1) ? B_V1 : B_V0) + vrel;

        // ---- GEMM1: S[32 x 32] = Q' x K(half)^T (already log2-scaled) ----
        float s[2][4][4];
        #pragma unroll
        for (int rt = 0; rt < 2; ++rt)
            #pragma unroll
            for (int j = 0; j < 4; ++j)
                { s[rt][j][0] = s[rt][j][1] = s[rt][j][2] = s[rt][j][3] = 0.f; }

        #pragma unroll
        for (int kk = 0; kk < 8; ++kk) {
            uint32_t A0[4], A1[4], B0[4], B1[4];
            ldsm_x4(A0, qA0 + kk * 32u);
            ldsm_x4(A1, qA1 + kk * 32u);
            ldsm_x4(B0, kB + kk * 32u);
            ldsm_x4(B1, kB + 16u * (TSTR * 2) + kk * 32u);
            mma_f16(s[0][0], A0, B0[0], B0[1]);
            mma_f16(s[0][1], A0, B0[2], B0[3]);
            mma_f16(s[0][2], A0, B1[0], B1[1]);
            mma_f16(s[0][3], A0, B1[2], B1[3]);
            mma_f16(s[1][0], A1, B0[0], B0[1]);
            mma_f16(s[1][1], A1, B0[2], B0[3]);
            mma_f16(s[1][2], A1, B1[0], B1[1]);
            mma_f16(s[1][3], A1, B1[2], B1[3]);
        }

        // ---- warp-local softmax (log2 domain) ----
        const bool diag = (jt >= 2 * it);
        #pragma unroll
        for (int rt = 0; rt < 2; ++rt) {
            const int r0 = q0 + 32 * rg + 16 * rt + g, r1 = r0 + 8;
            float t0 = -1e30f, t1 = -1e30f;
            #pragma unroll
            for (int j = 0; j < 4; ++j) {
                if (diag) {
                    int col = k0 + 32 * half + 8 * j + 2 * lq;
                    if (col     > r0) s[rt][j][0] = -1e30f;
                    if (col + 1 > r0) s[rt][j][1] = -1e30f;
                    if (col     > r1) s[rt][j][2] = -1e30f;
                    if (col + 1 > r1) s[rt][j][3] = -1e30f;
                }
                t0 = fmaxf(t0, fmaxf(s[rt][j][0], s[rt][j][1]));
                t1 = fmaxf(t1, fmaxf(s[rt][j][2], s[rt][j][3]));
            }
            t0 = fmaxf(t0, __shfl_xor_sync(0xffffffffu, t0, 1));
            t0 = fmaxf(t0, __shfl_xor_sync(0xffffffffu, t0, 2));
            t1 = fmaxf(t1, __shfl_xor_sync(0xffffffffu, t1, 1));
            t1 = fmaxf(t1, __shfl_xor_sync(0xffffffffu, t1, 2));

            // mm >= kMInit always, so mn >= kMInit: fully-masked half-rows
            // give p = ex2(-1e30 - mn) = 0 with no guard flags.
            const float mn0 = fmaxf(mm[2 * rt], t0), mn1 = fmaxf(mm[2 * rt + 1], t1);
            const float al0 = fast_ex2(mm[2 * rt] - mn0), al1 = fast_ex2(mm[2 * rt + 1] - mn1);
            mm[2 * rt] = mn0; mm[2 * rt + 1] = mn1;

            float rs0 = 0.f, rs1 = 0.f;
            #pragma unroll
            for (int j = 0; j < 4; ++j) {
                float p0 = fast_ex2(s[rt][j][0] - mn0);
                float p1 = fast_ex2(s[rt][j][1] - mn0);
                float p2 = fast_ex2(s[rt][j][2] - mn1);
                float p3 = fast_ex2(s[rt][j][3] - mn1);
                __half2 h0 = __floats2half2_rn(p0, p1);
                __half2 h1 = __floats2half2_rn(p2, p3);
                rs0 += __low2float(h0) + __high2float(h0);   // sum what GEMM2 sees
                rs1 += __low2float(h1) + __high2float(h1);
                *reinterpret_cast<__half2*>(&Ph[(16 * rt + g) * PSTR + 8 * j + 2 * lq])     = h0;
                *reinterpret_cast<__half2*>(&Ph[(16 * rt + g + 8) * PSTR + 8 * j + 2 * lq]) = h1;
            }
            rs0 += __shfl_xor_sync(0xffffffffu, rs0, 1);
            rs0 += __shfl_xor_sync(0xffffffffu, rs0, 2);
            rs1 += __shfl_xor_sync(0xffffffffu, rs1, 1);
            rs1 += __shfl_xor_sync(0xffffffffu, rs1, 2);
            ll[2 * rt]     = ll[2 * rt] * al0 + rs0;
            ll[2 * rt + 1] = ll[2 * rt + 1] * al1 + rs1;

            // skip the 128-FMUL rescale when the whole warp's max is unchanged
            bool need = (al0 != 1.0f) || (al1 != 1.0f);
            if (__any_sync(0xffffffffu, need)) {
                #pragma unroll
                for (int jn = 0; jn < 16; ++jn) {
                    o[rt][jn][0] *= al0; o[rt][jn][1] *= al0;
                    o[rt][jn][2] *= al1; o[rt][jn][3] *= al1;
                }
            }
        }
        __syncwarp();   // P visible within the warp

        // ---- GEMM2: O[32 x 128] += P(32x32) x V(half keys) ----
        #pragma unroll
        for (int kk = 0; kk < 2; ++kk) {
            uint32_t PA0[4], PA1[4];
            ldsm_x4(PA0, pA0 + kk * 32u);
            ldsm_x4(PA1, pA1 + kk * 32u);
            const uint32_t vkk = vB + (uint32_t)(kk * 16 * (TSTR * 2));
            #pragma unroll
            for (int jp = 0; jp < 8; ++jp) {
                uint32_t VB[4];
                ldsm_x4_t(VB, vkk + jp * 32u);
                mma_f16(o[0][2 * jp],     PA0, VB[0], VB[1]);
                mma_f16(o[0][2 * jp + 1], PA0, VB[2], VB[3]);
                mma_f16(o[1][2 * jp],     PA1, VB[0], VB[1]);
                mma_f16(o[1][2 * jp + 1], PA1, VB[2], VB[3]);
            }
        }
    }

    // ================= final merge of the two key-halves =================
    if (lq == 0) {
        #pragma unroll
        for (int i = 0; i < 4; ++i) {
            int rloc = 32 * rg + 16 * (i >> 1) + g + 8 * (i & 1);
            MLp[half * 256 + 2 * rloc]     = mm[i];
            MLp[half * 256 + 2 * rloc + 1] = ll[i];
        }
    }
    __syncthreads();
    float coef[4];
    #pragma unroll
    for (int i = 0; i < 4; ++i) {
        int rloc = 32 * rg + 16 * (i >> 1) + g + 8 * (i & 1);
        float mo = MLp[(1 - half) * 256 + 2 * rloc];
        float lo = MLp[(1 - half) * 256 + 2 * rloc + 1];
        float ms = fmaxf(mm[i], mo);
        float lt = ll[i] * fast_ex2(mm[i] - ms) + lo * fast_ex2(mo - ms);
        coef[i] = fast_ex2(mm[i] - ms) / lt;
    }
    __syncthreads();

    if (half == 0) {
        #pragma unroll
        for (int rt = 0; rt < 2; ++rt)
            #pragma unroll
            for (int jn = 0; jn < 16; ++jn) {
                int d = 8 * jn + 2 * lq;
                int r0 = 32 * rg + 16 * rt + g;
                MRG[r0 * 132 + d]           = o[rt][jn][0] * coef[2 * rt];
                MRG[r0 * 132 + d + 1]       = o[rt][jn][1] * coef[2 * rt];
                MRG[(r0 + 8) * 132 + d]     = o[rt][jn][2] * coef[2 * rt + 1];
                MRG[(r0 + 8) * 132 + d + 1] = o[rt][jn][3] * coef[2 * rt + 1];
            }
    }
    __syncthreads();
    if (half == 1) {
        const size_t gbase = (size_t)bh * kL * kD;
        #pragma unroll
        for (int rt = 0; rt < 2; ++rt)
            #pragma unroll
            for (int jn = 0; jn < 16; ++jn) {
                int d = 8 * jn + 2 * lq;
                int r0 = 32 * rg + 16 * rt + g;
                float2 w0, w1;
                w0.x = MRG[r0 * 132 + d]           + o[rt][jn][0] * coef[2 * rt];
                w0.y = MRG[r0 * 132 + d + 1]       + o[rt][jn][1] * coef[2 * rt];
                w1.x = MRG[(r0 + 8) * 132 + d]     + o[rt][jn][2] * coef[2 * rt + 1];
                w1.y = MRG[(r0 + 8) * 132 + d + 1] + o[rt][jn][3] * coef[2 * rt + 1];
                *reinterpret_cast<float2*>(&gout[gbase + (size_t)(q0 + r0) * kD + d])     = w0;
                *reinterpret_cast<float2*>(&gout[gbase + (size_t)(q0 + r0 + 8) * kD + d]) = w1;
            }
    }
}

extern "C" void kernel_launch(void* const* d_in, const int* in_sizes, int n_in,
                              void* d_out, int out_size) {
    (void)in_sizes; (void)n_in; (void)out_size;
    const float* q = (const float*)d_in[0];
    const float* k = (const float*)d_in[1];
    const float* v = (const float*)d_in[2];
    float* out = (float*)d_out;

    convert_kv_f16<<<2048, 256>>>(k, v);

    cudaFuncSetAttribute(fa_f16_kernel,
                         cudaFuncAttributeMaxDynamicSharedMemorySize, SMEM_BYTES);
    dim3 grid(kL / BR, kBH);   // 16 q-tiles x 32 heads
    fa_f16_kernel<<<grid, NTHR, SMEM_BYTES>>>(q, out);
}

// round 13
// speedup vs baseline: 2.4249x; 1.1271x over previous
#include <cuda_runtime.h>
#include <cuda_fp16.h>
#include <cstdint>

// Causal prefill attention, q,k,v,out: [B,H,L,D] fp32. B=2 H=16 L=2048 D=128.
// Kernel 1: convert k/v fp32 -> fp16 (RN) into static device buffers.
// Kernel 2: flash-attention-2, fp16 mma.sync.m16n8k16 (fp32 accum).
// R13: BR=64, 4 warps, 2 CTAs/SM (two independent barrier domains per SM so
// one CTA's MMAs overlap the other's softmax). Per-warp structure identical
// to the R11/12 winner: warp (rg, half) = 32 query rows x 32-key half,
// per-warp online softmax, one O/l/m merge at the end.
// K/V double-buffered via cp.async; all MMA operands ldmatrix-fed.
// Q converted + pre-scaled by log2(e)/sqrt(D) inline.

namespace {
constexpr int kL = 2048, kD = 128, kBH = 32;
constexpr int BR = 64, BC = 64, NTHR = 128;
constexpr int kN = kBH * kL * kD;
constexpr float kScaleLog2 = 0.12751745210670913f;  // (1/sqrt(128))*log2(e)
constexpr float kMInit = -60.0f;

// fp16 smem strides (halves) and byte offsets
constexpr int TSTR = 136;   // 272 B == 16 mod 128 -> ldsm conflict-free
constexpr int PSTR = 40;    // 80 B -> 8 distinct 16B groups
constexpr int B_Q  = 0;                     // 64*272 = 17408
constexpr int B_K0 = 17408;
constexpr int B_K1 = 34816;
constexpr int B_V0 = 52224;
constexpr int B_V1 = 69632;
constexpr int B_P  = 87040;                 // 4 warps x 32*80 = 10240
constexpr int B_ML = 97280;                 // 256 f32 = 1024
constexpr int SMEM_BYTES = 98304;           // x2 CTAs = 196608 <= 228KB/SM
constexpr int B_MRG = B_K0;                 // epilogue merge: 64*132*4 = 33792 B
}

__device__ __half g_k16[kN];
__device__ __half g_v16[kN];

__global__ void convert_kv_f16(const float* __restrict__ k,
                               const float* __restrict__ v) {
    const int n4 = kN / 4;
    for (int t = blockIdx.x * blockDim.x + threadIdx.x; t < 2 * n4;
         t += gridDim.x * blockDim.x) {
        int which = t / n4, i = t - which * n4;
        const float4* src = (const float4*)(which == 0 ? k : v);
        __half* dst = (which == 0 ? g_k16 : g_v16);
        float4 s = src[i];
        __half2 lo = __floats2half2_rn(s.x, s.y);
        __half2 hi = __floats2half2_rn(s.z, s.w);
        uint2 w;
        w.x = *reinterpret_cast<uint32_t*>(&lo);
        w.y = *reinterpret_cast<uint32_t*>(&hi);
        reinterpret_cast<uint2*>(dst)[i] = w;
    }
}

__device__ __forceinline__ float fast_ex2(float x) {
    float y;
    asm("ex2.approx.f32 %0, %1;" : "=f"(y) : "f"(x));
    return y;
}
__device__ __forceinline__ uint32_t smem_u32(const void* p) {
    uint32_t a;
    asm("{ .reg .u64 t; cvta.to.shared.u64 t, %1; cvt.u32.u64 %0, t; }" : "=r"(a) : "l"(p));
    return a;
}
__device__ __forceinline__ void ldsm_x4(uint32_t r[4], uint32_t addr) {
    asm volatile("ldmatrix.sync.aligned.m8n8.x4.shared.b16 {%0,%1,%2,%3}, [%4];"
                 : "=r"(r[0]), "=r"(r[1]), "=r"(r[2]), "=r"(r[3]) : "r"(addr));
}
__device__ __forceinline__ void ldsm_x4_t(uint32_t r[4], uint32_t addr) {
    asm volatile("ldmatrix.sync.aligned.m8n8.x4.trans.shared.b16 {%0,%1,%2,%3}, [%4];"
                 : "=r"(r[0]), "=r"(r[1]), "=r"(r[2]), "=r"(r[3]) : "r"(addr));
}
__device__ __forceinline__ void mma_f16(float c[4], const uint32_t a[4],
                                        uint32_t b0, uint32_t b1) {
    asm volatile(
        "mma.sync.aligned.m16n8k16.row.col.f32.f16.f16.f32 "
        "{%0,%1,%2,%3}, {%4,%5,%6,%7}, {%8,%9}, {%0,%1,%2,%3};\n"
        : "+f"(c[0]), "+f"(c[1]), "+f"(c[2]), "+f"(c[3])
        : "r"(a[0]), "r"(a[1]), "r"(a[2]), "r"(a[3]), "r"(b0), "r"(b1));
}

// async-stage one 64x128 fp16 tile (16B copies)
__device__ __forceinline__ void stage_tile16(uint32_t dst, const __half* __restrict__ src,
                                             int k0, int tid) {
    #pragma unroll
    for (int i = 0; i < 8; ++i) {
        int lin = tid + i * NTHR;
        int r = lin >> 4, c = lin & 15;
        const __half* p = src + (size_t)(k0 + r) * kD + c * 8;
        uint32_t d = dst + (uint32_t)(r * (TSTR * 2) + c * 16);
        asm volatile("cp.async.ca.shared.global [%0], [%1], 16;" :: "r"(d), "l"(p));
    }
}

__global__ __launch_bounds__(NTHR, 2)
void fa_f16_kernel(const float* __restrict__ gqf, float* __restrict__ gout) {
    extern __shared__ char smem[];
    const uint32_t sb = smem_u32(smem);
    float* MLp = reinterpret_cast<float*>(smem + B_ML);
    float* MRG = reinterpret_cast<float*>(smem + B_MRG);

    const int tid  = threadIdx.x;
    const int lane = tid & 31;
    const int wid  = tid >> 5;           // 0..3
    const int rg   = wid >> 1;           // row-group 0..1 (32 rows each)
    const int half = wid & 1;            // key half within each BC tile
    const int g    = lane >> 2;
    const int lq   = lane & 3;
    const int l15  = lane & 15;

    // ---- ldmatrix base addresses (bytes) ----
    const int chi = (lane >> 4) & 1;
    const uint32_t qA0 = sb + B_Q + (uint32_t)((32 * rg + l15) * (TSTR * 2) + chi * 16);
    const uint32_t qA1 = qA0 + (uint32_t)(16 * TSTR * 2);
    const uint32_t pW  = sb + B_P + (uint32_t)(wid * 32 * PSTR * 2);
    const uint32_t pA0 = pW + (uint32_t)(l15 * (PSTR * 2) + chi * 16);
    const uint32_t pA1 = pA0 + (uint32_t)(16 * PSTR * 2);
    const uint32_t krel = (uint32_t)((32 * half + ((lane >> 4) << 3) + (lane & 7)) * (TSTR * 2)
                                     + ((lane >> 3) & 1) * 16);
    const uint32_t vrel = (uint32_t)((32 * half + l15) * (TSTR * 2) + ((lane >> 4) & 1) * 16);

    const int it = (int)gridDim.x - 1 - (int)blockIdx.x;   // heavy tiles first
    const int bh = blockIdx.y;
    const size_t base = (size_t)bh * kL * kD;
    const int q0 = it * BR;
    const __half* gk = g_k16 + base;
    const __half* gv = g_v16 + base;
    __half* Ph = reinterpret_cast<__half*>(smem + B_P) + wid * 32 * PSTR;

    // ---- prologue: stage K(0)/V(0) async; convert+prescale Q inline ----
    stage_tile16(sb + B_K0, gk, 0, tid);
    stage_tile16(sb + B_V0, gv, 0, tid);
    asm volatile("cp.async.commit_group;" ::: "memory");

    {
        __half* Qh = reinterpret_cast<__half*>(smem + B_Q);
        const float* qsrc = gqf + base;
        #pragma unroll
        for (int i = 0; i < 16; ++i) {       // 64x128 f32 -> fp16 (prescaled)
            int lin = tid + i * NTHR;
            int r = lin >> 5, c4 = (lin & 31) << 2;
            float4 t = *reinterpret_cast<const float4*>(&qsrc[(size_t)(q0 + r) * kD + c4]);
            __half2 h0 = __floats2half2_rn(t.x * kScaleLog2, t.y * kScaleLog2);
            __half2 h1 = __floats2half2_rn(t.z * kScaleLog2, t.w * kScaleLog2);
            uint2 w;
            w.x = *reinterpret_cast<uint32_t*>(&h0);
            w.y = *reinterpret_cast<uint32_t*>(&h1);
            *reinterpret_cast<uint2*>(&Qh[r * TSTR + c4]) = w;
        }
    }

    float o[2][16][4];
    #pragma unroll
    for (int rt = 0; rt < 2; ++rt)
        #pragma unroll
        for (int jn = 0; jn < 16; ++jn)
            { o[rt][jn][0] = o[rt][jn][1] = o[rt][jn][2] = o[rt][jn][3] = 0.f; }
    float mm[4] = {kMInit, kMInit, kMInit, kMInit};
    float ll[4] = {0.f, 0.f, 0.f, 0.f};

    const int njt = it + 1;
    for (int jt = 0; jt < njt; ++jt) {
        const int k0 = jt * BC;

        asm volatile("cp.async.wait_group 0;" ::: "memory");   // K(jt),V(jt) resident
        __syncthreads();   // also covers Q visibility on jt==0

        if (jt + 1 < njt) {
            stage_tile16(sb + ((jt & 1) ? B_K0 : B_K1), gk, k0 + BC, tid);
            stage_tile16(sb + ((jt & 1) ? B_V0 : B_V1), gv, k0 + BC, tid);
            asm volatile("cp.async.commit_group;" ::: "memory");
        }

        const uint32_t kB = sb + (uint32_t)((jt & 1) ? B_K1 : B_K0) + krel;
        const uint32_t vB = sb + (uint32_t)((jt & 1) ? B_V1 : B_V0) + vrel;

        // ---- GEMM1: S[32 x 32] = Q' x K(half)^T (already log2-scaled) ----
        float s[2][4][4];
        #pragma unroll
        for (int rt = 0; rt < 2; ++rt)
            #pragma unroll
            for (int j = 0; j < 4; ++j)
                { s[rt][j][0] = s[rt][j][1] = s[rt][j][2] = s[rt][j][3] = 0.f; }

        #pragma unroll
        for (int kk = 0; kk < 8; ++kk) {
            uint32_t A0[4], A1[4], B0[4], B1[4];
            ldsm_x4(A0, qA0 + kk * 32u);
            ldsm_x4(A1, qA1 + kk * 32u);
            ldsm_x4(B0, kB + kk * 32u);
            ldsm_x4(B1, kB + 16u * (TSTR * 2) + kk * 32u);
            mma_f16(s[0][0], A0, B0[0], B0[1]);
            mma_f16(s[0][1], A0, B0[2], B0[3]);
            mma_f16(s[0][2], A0, B1[0], B1[1]);
            mma_f16(s[0][3], A0, B1[2], B1[3]);
            mma_f16(s[1][0], A1, B0[0], B0[1]);
            mma_f16(s[1][1], A1, B0[2], B0[3]);
            mma_f16(s[1][2], A1, B1[0], B1[1]);
            mma_f16(s[1][3], A1, B1[2], B1[3]);
        }

        // ---- warp-local softmax (log2 domain) ----
        const bool diag = (jt == it);
        #pragma unroll
        for (int rt = 0; rt < 2; ++rt) {
            const int r0 = q0 + 32 * rg + 16 * rt + g, r1 = r0 + 8;
            float t0 = -1e30f, t1 = -1e30f;
            #pragma unroll
            for (int j = 0; j < 4; ++j) {
                if (diag) {
                    int col = k0 + 32 * half + 8 * j + 2 * lq;
                    if (col     > r0) s[rt][j][0] = -1e30f;
                    if (col + 1 > r0) s[rt][j][1] = -1e30f;
                    if (col     > r1) s[rt][j][2] = -1e30f;
                    if (col + 1 > r1) s[rt][j][3] = -1e30f;
                }
                t0 = fmaxf(t0, fmaxf(s[rt][j][0], s[rt][j][1]));
                t1 = fmaxf(t1, fmaxf(s[rt][j][2], s[rt][j][3]));
            }
            t0 = fmaxf(t0, __shfl_xor_sync(0xffffffffu, t0, 1));
            t0 = fmaxf(t0, __shfl_xor_sync(0xffffffffu, t0, 2));
            t1 = fmaxf(t1, __shfl_xor_sync(0xffffffffu, t1, 1));
            t1 = fmaxf(t1, __shfl_xor_sync(0xffffffffu, t1, 2));

            // mm >= kMInit, so masked half-rows give p = ex2(-huge) = 0 naturally
            const float mn0 = fmaxf(mm[2 * rt], t0), mn1 = fmaxf(mm[2 * rt + 1], t1);
            const float al0 = fast_ex2(mm[2 * rt] - mn0), al1 = fast_ex2(mm[2 * rt + 1] - mn1);
            mm[2 * rt] = mn0; mm[2 * rt + 1] = mn1;

            float rs0 = 0.f, rs1 = 0.f;
            #pragma unroll
            for (int j = 0; j < 4; ++j) {
                float p0 = fast_ex2(s[rt][j][0] - mn0);
                float p1 = fast_ex2(s[rt][j][1] - mn0);
                float p2 = fast_ex2(s[rt][j][2] - mn1);
                float p3 = fast_ex2(s[rt][j][3] - mn1);
                __half2 h0 = __floats2half2_rn(p0, p1);
                __half2 h1 = __floats2half2_rn(p2, p3);
                rs0 += __low2float(h0) + __high2float(h0);   // sum what GEMM2 sees
                rs1 += __low2float(h1) + __high2float(h1);
                *reinterpret_cast<__half2*>(&Ph[(16 * rt + g) * PSTR + 8 * j + 2 * lq])     = h0;
                *reinterpret_cast<__half2*>(&Ph[(16 * rt + g + 8) * PSTR + 8 * j + 2 * lq]) = h1;
            }
            rs0 += __shfl_xor_sync(0xffffffffu, rs0, 1);
            rs0 += __shfl_xor_sync(0xffffffffu, rs0, 2);
            rs1 += __shfl_xor_sync(0xffffffffu, rs1, 1);
            rs1 += __shfl_xor_sync(0xffffffffu, rs1, 2);
            ll[2 * rt]     = ll[2 * rt] * al0 + rs0;
            ll[2 * rt + 1] = ll[2 * rt + 1] * al1 + rs1;

            bool need = (al0 != 1.0f) || (al1 != 1.0f);
            if (__any_sync(0xffffffffu, need)) {
                #pragma unroll
                for (int jn = 0; jn < 16; ++jn) {
                    o[rt][jn][0] *= al0; o[rt][jn][1] *= al0;
                    o[rt][jn][2] *= al1; o[rt][jn][3] *= al1;
                }
            }
        }
        __syncwarp();   // P visible within the warp

        // ---- GEMM2: O[32 x 128] += P(32x32) x V(half keys) ----
        #pragma unroll
        for (int kk = 0; kk < 2; ++kk) {
            uint32_t PA0[4], PA1[4];
            ldsm_x4(PA0, pA0 + kk * 32u);
            ldsm_x4(PA1, pA1 + kk * 32u);
            const uint32_t vkk = vB + (uint32_t)(kk * 16 * (TSTR * 2));
            #pragma unroll
            for (int jp = 0; jp < 8; ++jp) {
                uint32_t VB[4];
                ldsm_x4_t(VB, vkk + jp * 32u);
                mma_f16(o[0][2 * jp],     PA0, VB[0], VB[1]);
                mma_f16(o[0][2 * jp + 1], PA0, VB[2], VB[3]);
                mma_f16(o[1][2 * jp],     PA1, VB[0], VB[1]);
                mma_f16(o[1][2 * jp + 1], PA1, VB[2], VB[3]);
            }
        }
    }

    // ================= final merge of the two key-halves =================
    if (lq == 0) {
        #pragma unroll
        for (int i = 0; i < 4; ++i) {
            int rloc = 32 * rg + 16 * (i >> 1) + g + 8 * (i & 1);
            MLp[half * 128 + 2 * rloc]     = mm[i];
            MLp[half * 128 + 2 * rloc + 1] = ll[i];
        }
    }
    __syncthreads();
    float coef[4];
    #pragma unroll
    for (int i = 0; i < 4; ++i) {
        int rloc = 32 * rg + 16 * (i >> 1) + g + 8 * (i & 1);
        float mo = MLp[(1 - half) * 128 + 2 * rloc];
        float lo = MLp[(1 - half) * 128 + 2 * rloc + 1];
        float ms = fmaxf(mm[i], mo);
        float lt = ll[i] * fast_ex2(mm[i] - ms) + lo * fast_ex2(mo - ms);
        coef[i] = fast_ex2(mm[i] - ms) / lt;
    }
    __syncthreads();

    if (half == 0) {
        #pragma unroll
        for (int rt = 0; rt < 2; ++rt)
            #pragma unroll
            for (int jn = 0; jn < 16; ++jn) {
                int d = 8 * jn + 2 * lq;
                int r0 = 32 * rg + 16 * rt + g;
                MRG[r0 * 132 + d]           = o[rt][jn][0] * coef[2 * rt];
                MRG[r0 * 132 + d + 1]       = o[rt][jn][1] * coef[2 * rt];
                MRG[(r0 + 8) * 132 + d]     = o[rt][jn][2] * coef[2 * rt + 1];
                MRG[(r0 + 8) * 132 + d + 1] = o[rt][jn][3] * coef[2 * rt + 1];
            }
    }
    __syncthreads();
    if (half == 1) {
        const size_t gbase = (size_t)bh * kL * kD;
        #pragma unroll
        for (int rt = 0; rt < 2; ++rt)
            #pragma unroll
            for (int jn = 0; jn < 16; ++jn) {
                int d = 8 * jn + 2 * lq;
                int r0 = 32 * rg + 16 * rt + g;
                float2 w0, w1;
                w0.x = MRG[r0 * 132 + d]           + o[rt][jn][0] * coef[2 * rt];
                w0.y = MRG[r0 * 132 + d + 1]       + o[rt][jn][1] * coef[2 * rt];
                w1.x = MRG[(r0 + 8) * 132 + d]     + o[rt][jn][2] * coef[2 * rt + 1];
                w1.y = MRG[(r0 + 8) * 132 + d + 1] + o[rt][jn][3] * coef[2 * rt + 1];
                *reinterpret_cast<float2*>(&gout[gbase + (size_t)(q0 + r0) * kD + d])     = w0;
                *reinterpret_cast<float2*>(&gout[gbase + (size_t)(q0 + r0 + 8) * kD + d]) = w1;
            }
    }
}

extern "C" void kernel_launch(void* const* d_in, const int* in_sizes, int n_in,
                              void* d_out, int out_size) {
    (void)in_sizes; (void)n_in; (void)out_size;
    const float* q = (const float*)d_in[0];
    const float* k = (const float*)d_in[1];
    const float* v = (const float*)d_in[2];
    float* out = (float*)d_out;

    convert_kv_f16<<<2048, 256>>>(k, v);

    cudaFuncSetAttribute(fa_f16_kernel,
                         cudaFuncAttributeMaxDynamicSharedMemorySize, SMEM_BYTES);
    dim3 grid(kL / BR, kBH);   // 32 q-tiles x 32 heads
    fa_f16_kernel<<<grid, NTHR, SMEM_BYTES>>>(q, out);
}

// round 14
// speedup vs baseline: 2.5207x; 1.0395x over previous
#include <cuda_runtime.h>
#include <cuda_fp16.h>
#include <cstdint>

// Causal prefill attention, q,k,v,out: [B,H,L,D] fp32. B=2 H=16 L=2048 D=128.
// Kernel 1: convert k/v fp32 -> fp16 (RN) into static device buffers.
// Kernel 2: flash-attention-2, fp16 mma.sync.m16n8k16 (fp32 accum).
// BR=64, 4 warps, 2 CTAs/SM (independent barrier domains). Warp (rg, half) =
// 32 query rows x 32-key half, per-warp online softmax, one merge at the end.
// R14: softmax row-sum l computed by MMA-with-ones fragments (lacc) instead of
// per-thread sums + shuffle reductions -> softmax serial chain shortened.
// K/V double-buffered via cp.async; all MMA operands ldmatrix-fed.
// Q converted + pre-scaled by log2(e)/sqrt(D) inline.

namespace {
constexpr int kL = 2048, kD = 128, kBH = 32;
constexpr int BR = 64, BC = 64, NTHR = 128;
constexpr int kN = kBH * kL * kD;
constexpr float kScaleLog2 = 0.12751745210670913f;  // (1/sqrt(128))*log2(e)
constexpr float kMInit = -60.0f;
constexpr uint32_t ONE2 = 0x3C003C00u;   // half2(1.0, 1.0)

// fp16 smem strides (halves) and byte offsets
constexpr int TSTR = 136;   // 272 B == 16 mod 128 -> ldsm conflict-free
constexpr int PSTR = 40;    // 80 B -> 8 distinct 16B groups
constexpr int B_Q  = 0;                     // 64*272 = 17408
constexpr int B_K0 = 17408;
constexpr int B_K1 = 34816;
constexpr int B_V0 = 52224;
constexpr int B_V1 = 69632;
constexpr int B_P  = 87040;                 // 4 warps x 32*80 = 10240
constexpr int B_ML = 97280;                 // 256 f32 = 1024
constexpr int SMEM_BYTES = 98304;           // x2 CTAs = 196608 <= 228KB/SM
constexpr int B_MRG = B_K0;                 // epilogue merge buffer
}

__device__ __half g_k16[kN];
__device__ __half g_v16[kN];

__global__ void convert_kv_f16(const float* __restrict__ k,
                               const float* __restrict__ v) {
    int i = blockIdx.x * blockDim.x + threadIdx.x;   // 0 .. kN/4-1
    float4 a = reinterpret_cast<const float4*>(k)[i];
    float4 b = reinterpret_cast<const float4*>(v)[i];
    __half2 a0 = __floats2half2_rn(a.x, a.y), a1 = __floats2half2_rn(a.z, a.w);
    __half2 b0 = __floats2half2_rn(b.x, b.y), b1 = __floats2half2_rn(b.z, b.w);
    uint2 wa, wb;
    wa.x = *reinterpret_cast<uint32_t*>(&a0); wa.y = *reinterpret_cast<uint32_t*>(&a1);
    wb.x = *reinterpret_cast<uint32_t*>(&b0); wb.y = *reinterpret_cast<uint32_t*>(&b1);
    reinterpret_cast<uint2*>(g_k16)[i] = wa;
    reinterpret_cast<uint2*>(g_v16)[i] = wb;
}

__device__ __forceinline__ float fast_ex2(float x) {
    float y;
    asm("ex2.approx.f32 %0, %1;" : "=f"(y) : "f"(x));
    return y;
}
__device__ __forceinline__ uint32_t smem_u32(const void* p) {
    uint32_t a;
    asm("{ .reg .u64 t; cvta.to.shared.u64 t, %1; cvt.u32.u64 %0, t; }" : "=r"(a) : "l"(p));
    return a;
}
__device__ __forceinline__ void ldsm_x4(uint32_t r[4], uint32_t addr) {
    asm volatile("ldmatrix.sync.aligned.m8n8.x4.shared.b16 {%0,%1,%2,%3}, [%4];"
                 : "=r"(r[0]), "=r"(r[1]), "=r"(r[2]), "=r"(r[3]) : "r"(addr));
}
__device__ __forceinline__ void ldsm_x4_t(uint32_t r[4], uint32_t addr) {
    asm volatile("ldmatrix.sync.aligned.m8n8.x4.trans.shared.b16 {%0,%1,%2,%3}, [%4];"
                 : "=r"(r[0]), "=r"(r[1]), "=r"(r[2]), "=r"(r[3]) : "r"(addr));
}
__device__ __forceinline__ void mma_f16(float c[4], const uint32_t a[4],
                                        uint32_t b0, uint32_t b1) {
    asm volatile(
        "mma.sync.aligned.m16n8k16.row.col.f32.f16.f16.f32 "
        "{%0,%1,%2,%3}, {%4,%5,%6,%7}, {%8,%9}, {%0,%1,%2,%3};\n"
        : "+f"(c[0]), "+f"(c[1]), "+f"(c[2]), "+f"(c[3])
        : "r"(a[0]), "r"(a[1]), "r"(a[2]), "r"(a[3]), "r"(b0), "r"(b1));
}

// async-stage one 64x128 fp16 tile (16B copies)
__device__ __forceinline__ void stage_tile16(uint32_t dst, const __half* __restrict__ src,
                                             int k0, int tid) {
    #pragma unroll
    for (int i = 0; i < 8; ++i) {
        int lin = tid + i * NTHR;
        int r = lin >> 4, c = lin & 15;
        const __half* p = src + (size_t)(k0 + r) * kD + c * 8;
        uint32_t d = dst + (uint32_t)(r * (TSTR * 2) + c * 16);
        asm volatile("cp.async.ca.shared.global [%0], [%1], 16;" :: "r"(d), "l"(p));
    }
}

__global__ __launch_bounds__(NTHR, 2)
void fa_f16_kernel(const float* __restrict__ gqf, float* __restrict__ gout) {
    extern __shared__ char smem[];
    const uint32_t sb = smem_u32(smem);
    float* MLp = reinterpret_cast<float*>(smem + B_ML);
    float* MRG = reinterpret_cast<float*>(smem + B_MRG);

    const int tid  = threadIdx.x;
    const int lane = tid & 31;
    const int wid  = tid >> 5;           // 0..3
    const int rg   = wid >> 1;           // row-group 0..1 (32 rows each)
    const int half = wid & 1;            // key half within each BC tile
    const int g    = lane >> 2;
    const int lq   = lane & 3;
    const int l15  = lane & 15;

    // ---- ldmatrix base addresses (bytes) ----
    const int chi = (lane >> 4) & 1;
    const uint32_t qA0 = sb + B_Q + (uint32_t)((32 * rg + l15) * (TSTR * 2) + chi * 16);
    const uint32_t qA1 = qA0 + (uint32_t)(16 * TSTR * 2);
    const uint32_t pW  = sb + B_P + (uint32_t)(wid * 32 * PSTR * 2);
    const uint32_t pA0 = pW + (uint32_t)(l15 * (PSTR * 2) + chi * 16);
    const uint32_t pA1 = pA0 + (uint32_t)(16 * PSTR * 2);
    const uint32_t krel = (uint32_t)((32 * half + ((lane >> 4) << 3) + (lane & 7)) * (TSTR * 2)
                                     + ((lane >> 3) & 1) * 16);
    const uint32_t vrel = (uint32_t)((32 * half + l15) * (TSTR * 2) + ((lane >> 4) & 1) * 16);

    const int it = (int)gridDim.x - 1 - (int)blockIdx.x;   // heavy tiles first
    const int bh = blockIdx.y;
    const size_t base = (size_t)bh * kL * kD;
    const int q0 = it * BR;
    const __half* gk = g_k16 + base;
    const __half* gv = g_v16 + base;
    __half* Ph = reinterpret_cast<__half*>(smem + B_P) + wid * 32 * PSTR;

    // ---- prologue: stage K(0)/V(0) async; convert+prescale Q inline ----
    stage_tile16(sb + B_K0, gk, 0, tid);
    stage_tile16(sb + B_V0, gv, 0, tid);
    asm volatile("cp.async.commit_group;" ::: "memory");

    {
        __half* Qh = reinterpret_cast<__half*>(smem + B_Q);
        const float* qsrc = gqf + base;
        #pragma unroll
        for (int i = 0; i < 16; ++i) {       // 64x128 f32 -> fp16 (prescaled)
            int lin = tid + i * NTHR;
            int r = lin >> 5, c4 = (lin & 31) << 2;
            float4 t = *reinterpret_cast<const float4*>(&qsrc[(size_t)(q0 + r) * kD + c4]);
            __half2 h0 = __floats2half2_rn(t.x * kScaleLog2, t.y * kScaleLog2);
            __half2 h1 = __floats2half2_rn(t.z * kScaleLog2, t.w * kScaleLog2);
            uint2 w;
            w.x = *reinterpret_cast<uint32_t*>(&h0);
            w.y = *reinterpret_cast<uint32_t*>(&h1);
            *reinterpret_cast<uint2*>(&Qh[r * TSTR + c4]) = w;
        }
    }

    float o[2][16][4];
    #pragma unroll
    for (int rt = 0; rt < 2; ++rt)
        #pragma unroll
        for (int jn = 0; jn < 16; ++jn)
            { o[rt][jn][0] = o[rt][jn][1] = o[rt][jn][2] = o[rt][jn][3] = 0.f; }
    float lacc[2][4];                     // row-sum accumulator fragments (MMA-with-ones)
    lacc[0][0] = lacc[0][1] = lacc[0][2] = lacc[0][3] = 0.f;
    lacc[1][0] = lacc[1][1] = lacc[1][2] = lacc[1][3] = 0.f;
    float mm[4] = {kMInit, kMInit, kMInit, kMInit};

    const int njt = it + 1;
    for (int jt = 0; jt < njt; ++jt) {
        const int k0 = jt * BC;

        asm volatile("cp.async.wait_group 0;" ::: "memory");   // K(jt),V(jt) resident
        __syncthreads();   // also covers Q visibility on jt==0

        if (jt + 1 < njt) {
            stage_tile16(sb + ((jt & 1) ? B_K0 : B_K1), gk, k0 + BC, tid);
            stage_tile16(sb + ((jt & 1) ? B_V0 : B_V1), gv, k0 + BC, tid);
            asm volatile("cp.async.commit_group;" ::: "memory");
        }

        const uint32_t kB = sb + (uint32_t)((jt & 1) ? B_K1 : B_K0) + krel;
        const uint32_t vB = sb + (uint32_t)((jt & 1) ? B_V1 : B_V0) + vrel;

        // ---- GEMM1: S[32 x 32] = Q' x K(half)^T (already log2-scaled) ----
        float s[2][4][4];
        #pragma unroll
        for (int rt = 0; rt < 2; ++rt)
            #pragma unroll
            for (int j = 0; j < 4; ++j)
                { s[rt][j][0] = s[rt][j][1] = s[rt][j][2] = s[rt][j][3] = 0.f; }

        #pragma unroll
        for (int kk = 0; kk < 8; ++kk) {
            uint32_t A0[4], A1[4], B0[4], B1[4];
            ldsm_x4(A0, qA0 + kk * 32u);
            ldsm_x4(A1, qA1 + kk * 32u);
            ldsm_x4(B0, kB + kk * 32u);
            ldsm_x4(B1, kB + 16u * (TSTR * 2) + kk * 32u);
            mma_f16(s[0][0], A0, B0[0], B0[1]);
            mma_f16(s[0][1], A0, B0[2], B0[3]);
            mma_f16(s[0][2], A0, B1[0], B1[1]);
            mma_f16(s[0][3], A0, B1[2], B1[3]);
            mma_f16(s[1][0], A1, B0[0], B0[1]);
            mma_f16(s[1][1], A1, B0[2], B0[3]);
            mma_f16(s[1][2], A1, B1[0], B1[1]);
            mma_f16(s[1][3], A1, B1[2], B1[3]);
        }

        // ---- warp-local softmax (log2 domain) ----
        const bool diag = (jt == it);
        #pragma unroll
        for (int rt = 0; rt < 2; ++rt) {
            const int r0 = q0 + 32 * rg + 16 * rt + g, r1 = r0 + 8;
            float t0 = -1e30f, t1 = -1e30f;
            #pragma unroll
            for (int j = 0; j < 4; ++j) {
                if (diag) {
                    int col = k0 + 32 * half + 8 * j + 2 * lq;
                    if (col     > r0) s[rt][j][0] = -1e30f;
                    if (col + 1 > r0) s[rt][j][1] = -1e30f;
                    if (col     > r1) s[rt][j][2] = -1e30f;
                    if (col + 1 > r1) s[rt][j][3] = -1e30f;
                }
                t0 = fmaxf(t0, fmaxf(s[rt][j][0], s[rt][j][1]));
                t1 = fmaxf(t1, fmaxf(s[rt][j][2], s[rt][j][3]));
            }
            t0 = fmaxf(t0, __shfl_xor_sync(0xffffffffu, t0, 1));
            t0 = fmaxf(t0, __shfl_xor_sync(0xffffffffu, t0, 2));
            t1 = fmaxf(t1, __shfl_xor_sync(0xffffffffu, t1, 1));
            t1 = fmaxf(t1, __shfl_xor_sync(0xffffffffu, t1, 2));

            // mm >= kMInit, so masked half-rows give p = ex2(-huge) = 0 naturally
            const float mn0 = fmaxf(mm[2 * rt], t0), mn1 = fmaxf(mm[2 * rt + 1], t1);
            const float al0 = fast_ex2(mm[2 * rt] - mn0), al1 = fast_ex2(mm[2 * rt + 1] - mn1);
            mm[2 * rt] = mn0; mm[2 * rt + 1] = mn1;

            #pragma unroll
            for (int j = 0; j < 4; ++j) {
                float p0 = fast_ex2(s[rt][j][0] - mn0);
                float p1 = fast_ex2(s[rt][j][1] - mn0);
                float p2 = fast_ex2(s[rt][j][2] - mn1);
                float p3 = fast_ex2(s[rt][j][3] - mn1);
                __half2 h0 = __floats2half2_rn(p0, p1);
                __half2 h1 = __floats2half2_rn(p2, p3);
                *reinterpret_cast<__half2*>(&Ph[(16 * rt + g) * PSTR + 8 * j + 2 * lq])     = h0;
                *reinterpret_cast<__half2*>(&Ph[(16 * rt + g + 8) * PSTR + 8 * j + 2 * lq]) = h1;
            }

            // rescale O and lacc by alpha (unconditional: vote never helps in practice)
            lacc[rt][0] *= al0; lacc[rt][1] *= al0;
            lacc[rt][2] *= al1; lacc[rt][3] *= al1;
            #pragma unroll
            for (int jn = 0; jn < 16; ++jn) {
                o[rt][jn][0] *= al0; o[rt][jn][1] *= al0;
                o[rt][jn][2] *= al1; o[rt][jn][3] *= al1;
            }
        }
        __syncwarp();   // P visible within the warp

        // ---- GEMM2: O[32 x 128] += P(32x32) x V(half keys); l += P x ones ----
        #pragma unroll
        for (int kk = 0; kk < 2; ++kk) {
            uint32_t PA0[4], PA1[4];
            ldsm_x4(PA0, pA0 + kk * 32u);
            ldsm_x4(PA1, pA1 + kk * 32u);
            mma_f16(lacc[0], PA0, ONE2, ONE2);   // exact fp16 row-sums of P
            mma_f16(lacc[1], PA1, ONE2, ONE2);
            const uint32_t vkk = vB + (uint32_t)(kk * 16 * (TSTR * 2));
            #pragma unroll
            for (int jp = 0; jp < 8; ++jp) {
                uint32_t VB[4];
                ldsm_x4_t(VB, vkk + jp * 32u);
                mma_f16(o[0][2 * jp],     PA0, VB[0], VB[1]);
                mma_f16(o[0][2 * jp + 1], PA0, VB[2], VB[3]);
                mma_f16(o[1][2 * jp],     PA1, VB[0], VB[1]);
                mma_f16(o[1][2 * jp + 1], PA1, VB[2], VB[3]);
            }
        }
    }

    // ================= final merge of the two key-halves =================
    // ll[i] for i = 2rt + rh lives in lacc[rt][2*rh] (columns duplicated)
    if (lq == 0) {
        #pragma unroll
        for (int i = 0; i < 4; ++i) {
            int rloc = 32 * rg + 16 * (i >> 1) + g + 8 * (i & 1);
            MLp[half * 128 + 2 * rloc]     = mm[i];
            MLp[half * 128 + 2 * rloc + 1] = lacc[i >> 1][(i & 1) * 2];
        }
    }
    __syncthreads();
    float coef[4];
    #pragma unroll
    for (int i = 0; i < 4; ++i) {
        int rloc = 32 * rg + 16 * (i >> 1) + g + 8 * (i & 1);
        float mo = MLp[(1 - half) * 128 + 2 * rloc];
        float lo = MLp[(1 - half) * 128 + 2 * rloc + 1];
        float ms = fmaxf(mm[i], mo);
        float lt = lacc[i >> 1][(i & 1) * 2] * fast_ex2(mm[i] - ms) + lo * fast_ex2(mo - ms);
        coef[i] = fast_ex2(mm[i] - ms) / lt;
    }
    __syncthreads();

    if (half == 0) {
        #pragma unroll
        for (int rt = 0; rt < 2; ++rt)
            #pragma unroll
            for (int jn = 0; jn < 16; ++jn) {
                int d = 8 * jn + 2 * lq;
                int r0 = 32 * rg + 16 * rt + g;
                MRG[r0 * 132 + d]           = o[rt][jn][0] * coef[2 * rt];
                MRG[r0 * 132 + d + 1]       = o[rt][jn][1] * coef[2 * rt];
                MRG[(r0 + 8) * 132 + d]     = o[rt][jn][2] * coef[2 * rt + 1];
                MRG[(r0 + 8) * 132 + d + 1] = o[rt][jn][3] * coef[2 * rt + 1];
            }
    }
    __syncthreads();
    if (half == 1) {
        const size_t gbase = (size_t)bh * kL * kD;
        #pragma unroll
        for (int rt = 0; rt < 2; ++rt)
            #pragma unroll
            for (int jn = 0; jn < 16; ++jn) {
                int d = 8 * jn + 2 * lq;
                int r0 = 32 * rg + 16 * rt + g;
                float2 w0, w1;
                w0.x = MRG[r0 * 132 + d]           + o[rt][jn][0] * coef[2 * rt];
                w0.y = MRG[r0 * 132 + d + 1]       + o[rt][jn][1] * coef[2 * rt];
                w1.x = MRG[(r0 + 8) * 132 + d]     + o[rt][jn][2] * coef[2 * rt + 1];
                w1.y = MRG[(r0 + 8) * 132 + d + 1] + o[rt][jn][3] * coef[2 * rt + 1];
                *reinterpret_cast<float2*>(&gout[gbase + (size_t)(q0 + r0) * kD + d])     = w0;
                *reinterpret_cast<float2*>(&gout[gbase + (size_t)(q0 + r0 + 8) * kD + d]) = w1;
            }
    }
}

extern "C" void kernel_launch(void* const* d_in, const int* in_sizes, int n_in,
                              void* d_out, int out_size) {
    (void)in_sizes; (void)n_in; (void)out_size;
    const float* q = (const float*)d_in[0];
    const float* k = (const float*)d_in[1];
    const float* v = (const float*)d_in[2];
    float* out = (float*)d_out;

    convert_kv_f16<<<kN / 4 / 256, 256>>>(k, v);

    cudaFuncSetAttribute(fa_f16_kernel,
                         cudaFuncAttributeMaxDynamicSharedMemorySize, SMEM_BYTES);
    dim3 grid(kL / BR, kBH);   // 32 q-tiles x 32 heads
    fa_f16_kernel<<<grid, NTHR, SMEM_BYTES>>>(q, out);
}

// round 15
// speedup vs baseline: 2.6674x; 1.0582x over previous
#include <cuda_runtime.h>
#include <cuda_fp16.h>
#include <cstdint>

// Causal prefill attention, q,k,v,out: [B,H,L,D] fp32. B=2 H=16 L=2048 D=128.
// Kernel 1: convert k/v fp32 -> fp16 (RN) into static device buffers.
// Kernel 2: flash-attention-2, fp16 mma.sync.m16n8k16 (fp32 accum).
// BR=64, 4 warps, 2 CTAs/SM. Warp (rg, half) = 32 query rows x 32-key half,
// per-warp online softmax, one merge at the end.
// R15: P stays in REGISTERS. The m16n8k16 C-fragment of GEMM1, packed to
// fp16 pairs per-thread, IS the A-fragment of GEMM2 (a0/a1 from even j,
// a2/a3 from odd j) -> no P smem, no syncwarp, no ldmatrix for P.
// K/V double-buffered via cp.async; Q/K/V operands ldmatrix-fed.
// Q converted + pre-scaled by log2(e)/sqrt(D) inline. Row-sum l via
// MMA-with-ones on the packed P fragments.

namespace {
constexpr int kL = 2048, kD = 128, kBH = 32;
constexpr int BR = 64, BC = 64, NTHR = 128;
constexpr int kN = kBH * kL * kD;
constexpr float kScaleLog2 = 0.12751745210670913f;  // (1/sqrt(128))*log2(e)
constexpr float kMInit = -60.0f;
constexpr uint32_t ONE2 = 0x3C003C00u;   // half2(1.0, 1.0)

// fp16 smem strides (halves) and byte offsets
constexpr int TSTR = 136;   // 272 B == 16 mod 128 -> ldsm conflict-free
constexpr int B_Q  = 0;                     // 64*272 = 17408
constexpr int B_K0 = 17408;
constexpr int B_K1 = 34816;
constexpr int B_V0 = 52224;
constexpr int B_V1 = 69632;
constexpr int B_ML = 87040;                 // 256 f32 = 1024
constexpr int SMEM_BYTES = 88064;           // x2 CTAs = 176128 <= 228KB/SM
constexpr int B_MRG = B_K0;                 // epilogue merge: 33792 B, fits K0+K1
}

__device__ __half g_k16[kN];
__device__ __half g_v16[kN];

__global__ void convert_kv_f16(const float* __restrict__ k,
                               const float* __restrict__ v) {
    int i = blockIdx.x * blockDim.x + threadIdx.x;   // 0 .. kN/4-1
    float4 a = reinterpret_cast<const float4*>(k)[i];
    float4 b = reinterpret_cast<const float4*>(v)[i];
    __half2 a0 = __floats2half2_rn(a.x, a.y), a1 = __floats2half2_rn(a.z, a.w);
    __half2 b0 = __floats2half2_rn(b.x, b.y), b1 = __floats2half2_rn(b.z, b.w);
    uint2 wa, wb;
    wa.x = *reinterpret_cast<uint32_t*>(&a0); wa.y = *reinterpret_cast<uint32_t*>(&a1);
    wb.x = *reinterpret_cast<uint32_t*>(&b0); wb.y = *reinterpret_cast<uint32_t*>(&b1);
    reinterpret_cast<uint2*>(g_k16)[i] = wa;
    reinterpret_cast<uint2*>(g_v16)[i] = wb;
}

__device__ __forceinline__ float fast_ex2(float x) {
    float y;
    asm("ex2.approx.f32 %0, %1;" : "=f"(y) : "f"(x));
    return y;
}
__device__ __forceinline__ uint32_t smem_u32(const void* p) {
    uint32_t a;
    asm("{ .reg .u64 t; cvta.to.shared.u64 t, %1; cvt.u32.u64 %0, t; }" : "=r"(a) : "l"(p));
    return a;
}
__device__ __forceinline__ void ldsm_x4(uint32_t r[4], uint32_t addr) {
    asm volatile("ldmatrix.sync.aligned.m8n8.x4.shared.b16 {%0,%1,%2,%3}, [%4];"
                 : "=r"(r[0]), "=r"(r[1]), "=r"(r[2]), "=r"(r[3]) : "r"(addr));
}
__device__ __forceinline__ void ldsm_x4_t(uint32_t r[4], uint32_t addr) {
    asm volatile("ldmatrix.sync.aligned.m8n8.x4.trans.shared.b16 {%0,%1,%2,%3}, [%4];"
                 : "=r"(r[0]), "=r"(r[1]), "=r"(r[2]), "=r"(r[3]) : "r"(addr));
}
__device__ __forceinline__ void mma_f16(float c[4], const uint32_t a[4],
                                        uint32_t b0, uint32_t b1) {
    asm volatile(
        "mma.sync.aligned.m16n8k16.row.col.f32.f16.f16.f32 "
        "{%0,%1,%2,%3}, {%4,%5,%6,%7}, {%8,%9}, {%0,%1,%2,%3};\n"
        : "+f"(c[0]), "+f"(c[1]), "+f"(c[2]), "+f"(c[3])
        : "r"(a[0]), "r"(a[1]), "r"(a[2]), "r"(a[3]), "r"(b0), "r"(b1));
}

// async-stage one 64x128 fp16 tile (16B copies)
__device__ __forceinline__ void stage_tile16(uint32_t dst, const __half* __restrict__ src,
                                             int k0, int tid) {
    #pragma unroll
    for (int i = 0; i < 8; ++i) {
        int lin = tid + i * NTHR;
        int r = lin >> 4, c = lin & 15;
        const __half* p = src + (size_t)(k0 + r) * kD + c * 8;
        uint32_t d = dst + (uint32_t)(r * (TSTR * 2) + c * 16);
        asm volatile("cp.async.ca.shared.global [%0], [%1], 16;" :: "r"(d), "l"(p));
    }
}

__global__ __launch_bounds__(NTHR, 2)
void fa_f16_kernel(const float* __restrict__ gqf, float* __restrict__ gout) {
    extern __shared__ char smem[];
    const uint32_t sb = smem_u32(smem);
    float* MLp = reinterpret_cast<float*>(smem + B_ML);
    float* MRG = reinterpret_cast<float*>(smem + B_MRG);

    const int tid  = threadIdx.x;
    const int lane = tid & 31;
    const int wid  = tid >> 5;           // 0..3
    const int rg   = wid >> 1;           // row-group 0..1 (32 rows each)
    const int half = wid & 1;            // key half within each BC tile
    const int g    = lane >> 2;
    const int lq   = lane & 3;
    const int l15  = lane & 15;

    // ---- ldmatrix base addresses (bytes) ----
    const int chi = (lane >> 4) & 1;
    const uint32_t qA0 = sb + B_Q + (uint32_t)((32 * rg + l15) * (TSTR * 2) + chi * 16);
    const uint32_t qA1 = qA0 + (uint32_t)(16 * TSTR * 2);
    const uint32_t krel = (uint32_t)((32 * half + ((lane >> 4) << 3) + (lane & 7)) * (TSTR * 2)
                                     + ((lane >> 3) & 1) * 16);
    const uint32_t vrel = (uint32_t)((32 * half + l15) * (TSTR * 2) + ((lane >> 4) & 1) * 16);

    const int it = (int)gridDim.x - 1 - (int)blockIdx.x;   // heavy tiles first
    const int bh = blockIdx.y;
    const size_t base = (size_t)bh * kL * kD;
    const int q0 = it * BR;
    const __half* gk = g_k16 + base;
    const __half* gv = g_v16 + base;

    // ---- prologue: stage K(0)/V(0) async; convert+prescale Q inline ----
    stage_tile16(sb + B_K0, gk, 0, tid);
    stage_tile16(sb + B_V0, gv, 0, tid);
    asm volatile("cp.async.commit_group;" ::: "memory");

    {
        __half* Qh = reinterpret_cast<__half*>(smem + B_Q);
        const float* qsrc = gqf + base;
        #pragma unroll
        for (int i = 0; i < 16; ++i) {       // 64x128 f32 -> fp16 (prescaled)
            int lin = tid + i * NTHR;
            int r = lin >> 5, c4 = (lin & 31) << 2;
            float4 t = *reinterpret_cast<const float4*>(&qsrc[(size_t)(q0 + r) * kD + c4]);
            __half2 h0 = __floats2half2_rn(t.x * kScaleLog2, t.y * kScaleLog2);
            __half2 h1 = __floats2half2_rn(t.z * kScaleLog2, t.w * kScaleLog2);
            uint2 w;
            w.x = *reinterpret_cast<uint32_t*>(&h0);
            w.y = *reinterpret_cast<uint32_t*>(&h1);
            *reinterpret_cast<uint2*>(&Qh[r * TSTR + c4]) = w;
        }
    }

    float o[2][16][4];
    #pragma unroll
    for (int rt = 0; rt < 2; ++rt)
        #pragma unroll
        for (int jn = 0; jn < 16; ++jn)
            { o[rt][jn][0] = o[rt][jn][1] = o[rt][jn][2] = o[rt][jn][3] = 0.f; }
    float lacc[2][4];                     // row-sum fragments (MMA-with-ones)
    lacc[0][0] = lacc[0][1] = lacc[0][2] = lacc[0][3] = 0.f;
    lacc[1][0] = lacc[1][1] = lacc[1][2] = lacc[1][3] = 0.f;
    float mm[4] = {kMInit, kMInit, kMInit, kMInit};

    const int njt = it + 1;
    for (int jt = 0; jt < njt; ++jt) {
        const int k0 = jt * BC;

        asm volatile("cp.async.wait_group 0;" ::: "memory");   // K(jt),V(jt) resident
        __syncthreads();   // also covers Q visibility on jt==0

        if (jt + 1 < njt) {
            stage_tile16(sb + ((jt & 1) ? B_K0 : B_K1), gk, k0 + BC, tid);
            stage_tile16(sb + ((jt & 1) ? B_V0 : B_V1), gv, k0 + BC, tid);
            asm volatile("cp.async.commit_group;" ::: "memory");
        }

        const uint32_t kB = sb + (uint32_t)((jt & 1) ? B_K1 : B_K0) + krel;
        const uint32_t vB = sb + (uint32_t)((jt & 1) ? B_V1 : B_V0) + vrel;

        // ---- GEMM1: S[32 x 32] = Q' x K(half)^T (already log2-scaled) ----
        float s[2][4][4];
        #pragma unroll
        for (int rt = 0; rt < 2; ++rt)
            #pragma unroll
            for (int j = 0; j < 4; ++j)
                { s[rt][j][0] = s[rt][j][1] = s[rt][j][2] = s[rt][j][3] = 0.f; }

        #pragma unroll
        for (int kk = 0; kk < 8; ++kk) {
            uint32_t A0[4], A1[4], B0[4], B1[4];
            ldsm_x4(A0, qA0 + kk * 32u);
            ldsm_x4(A1, qA1 + kk * 32u);
            ldsm_x4(B0, kB + kk * 32u);
            ldsm_x4(B1, kB + 16u * (TSTR * 2) + kk * 32u);
            mma_f16(s[0][0], A0, B0[0], B0[1]);
            mma_f16(s[0][1], A0, B0[2], B0[3]);
            mma_f16(s[0][2], A0, B1[0], B1[1]);
            mma_f16(s[0][3], A0, B1[2], B1[3]);
            mma_f16(s[1][0], A1, B0[0], B0[1]);
            mma_f16(s[1][1], A1, B0[2], B0[3]);
            mma_f16(s[1][2], A1, B1[0], B1[1]);
            mma_f16(s[1][3], A1, B1[2], B1[3]);
        }

        // ---- warp-local softmax (log2 domain); P packed into A-fragments ----
        const bool diag = (jt == it);
        uint32_t pa[2][2][4];   // [rt][key chunk kk][a0..a3]
        #pragma unroll
        for (int rt = 0; rt < 2; ++rt) {
            const int r0 = q0 + 32 * rg + 16 * rt + g, r1 = r0 + 8;
            float t0 = -1e30f, t1 = -1e30f;
            #pragma unroll
            for (int j = 0; j < 4; ++j) {
                if (diag) {
                    int col = k0 + 32 * half + 8 * j + 2 * lq;
                    if (col     > r0) s[rt][j][0] = -1e30f;
                    if (col + 1 > r0) s[rt][j][1] = -1e30f;
                    if (col     > r1) s[rt][j][2] = -1e30f;
                    if (col + 1 > r1) s[rt][j][3] = -1e30f;
                }
                t0 = fmaxf(t0, fmaxf(s[rt][j][0], s[rt][j][1]));
                t1 = fmaxf(t1, fmaxf(s[rt][j][2], s[rt][j][3]));
            }
            t0 = fmaxf(t0, __shfl_xor_sync(0xffffffffu, t0, 1));
            t0 = fmaxf(t0, __shfl_xor_sync(0xffffffffu, t0, 2));
            t1 = fmaxf(t1, __shfl_xor_sync(0xffffffffu, t1, 1));
            t1 = fmaxf(t1, __shfl_xor_sync(0xffffffffu, t1, 2));

            // mm >= kMInit, so masked half-rows give p = ex2(-huge) = 0 naturally
            const float mn0 = fmaxf(mm[2 * rt], t0), mn1 = fmaxf(mm[2 * rt + 1], t1);
            const float al0 = fast_ex2(mm[2 * rt] - mn0), al1 = fast_ex2(mm[2 * rt + 1] - mn1);
            mm[2 * rt] = mn0; mm[2 * rt + 1] = mn1;

            // exp + pack: C-fragment (rows g,g+8; cols 8j+2lq,+1) -> A-fragment
            //   chunk kk = j>>1;  j even -> a0/a1,  j odd -> a2/a3
            #pragma unroll
            for (int j = 0; j < 4; ++j) {
                float p0 = fast_ex2(s[rt][j][0] - mn0);
                float p1 = fast_ex2(s[rt][j][1] - mn0);
                float p2 = fast_ex2(s[rt][j][2] - mn1);
                float p3 = fast_ex2(s[rt][j][3] - mn1);
                __half2 h0 = __floats2half2_rn(p0, p1);   // row g
                __half2 h1 = __floats2half2_rn(p2, p3);   // row g+8
                pa[rt][j >> 1][(j & 1) * 2]     = *reinterpret_cast<uint32_t*>(&h0);
                pa[rt][j >> 1][(j & 1) * 2 + 1] = *reinterpret_cast<uint32_t*>(&h1);
            }

            // rescale O and lacc by alpha
            lacc[rt][0] *= al0; lacc[rt][1] *= al0;
            lacc[rt][2] *= al1; lacc[rt][3] *= al1;
            #pragma unroll
            for (int jn = 0; jn < 16; ++jn) {
                o[rt][jn][0] *= al0; o[rt][jn][1] *= al0;
                o[rt][jn][2] *= al1; o[rt][jn][3] *= al1;
            }
        }

        // ---- GEMM2: O[32 x 128] += P(32x32) x V(half keys); l += P x ones ----
        #pragma unroll
        for (int kk = 0; kk < 2; ++kk) {
            mma_f16(lacc[0], pa[0][kk], ONE2, ONE2);   // exact fp16 row-sums of P
            mma_f16(lacc[1], pa[1][kk], ONE2, ONE2);
            const uint32_t vkk = vB + (uint32_t)(kk * 16 * (TSTR * 2));
            #pragma unroll
            for (int jp = 0; jp < 8; ++jp) {
                uint32_t VB[4];
                ldsm_x4_t(VB, vkk + jp * 32u);
                mma_f16(o[0][2 * jp],     pa[0][kk], VB[0], VB[1]);
                mma_f16(o[0][2 * jp + 1], pa[0][kk], VB[2], VB[3]);
                mma_f16(o[1][2 * jp],     pa[1][kk], VB[0], VB[1]);
                mma_f16(o[1][2 * jp + 1], pa[1][kk], VB[2], VB[3]);
            }
        }
    }

    // ================= final merge of the two key-halves =================
    // ll[i] for i = 2rt + rh lives in lacc[rt][2*rh] (columns duplicated)
    if (lq == 0) {
        #pragma unroll
        for (int i = 0; i < 4; ++i) {
            int rloc = 32 * rg + 16 * (i >> 1) + g + 8 * (i & 1);
            MLp[half * 128 + 2 * rloc]     = mm[i];
            MLp[half * 128 + 2 * rloc + 1] = lacc[i >> 1][(i & 1) * 2];
        }
    }
    __syncthreads();
    float coef[4];
    #pragma unroll
    for (int i = 0; i < 4; ++i) {
        int rloc = 32 * rg + 16 * (i >> 1) + g + 8 * (i & 1);
        float mo = MLp[(1 - half) * 128 + 2 * rloc];
        float lo = MLp[(1 - half) * 128 + 2 * rloc + 1];
        float ms = fmaxf(mm[i], mo);
        float lt = lacc[i >> 1][(i & 1) * 2] * fast_ex2(mm[i] - ms) + lo * fast_ex2(mo - ms);
        coef[i] = fast_ex2(mm[i] - ms) / lt;
    }
    __syncthreads();

    if (half == 0) {
        #pragma unroll
        for (int rt = 0; rt < 2; ++rt)
            #pragma unroll
            for (int jn = 0; jn < 16; ++jn) {
                int d = 8 * jn + 2 * lq;
                int r0 = 32 * rg + 16 * rt + g;
                MRG[r0 * 132 + d]           = o[rt][jn][0] * coef[2 * rt];
                MRG[r0 * 132 + d + 1]       = o[rt][jn][1] * coef[2 * rt];
                MRG[(r0 + 8) * 132 + d]     = o[rt][jn][2] * coef[2 * rt + 1];
                MRG[(r0 + 8) * 132 + d + 1] = o[rt][jn][3] * coef[2 * rt + 1];
            }
    }
    __syncthreads();
    if (half == 1) {
        const size_t gbase = (size_t)bh * kL * kD;
        #pragma unroll
        for (int rt = 0; rt < 2; ++rt)
            #pragma unroll
            for (int jn = 0; jn < 16; ++jn) {
                int d = 8 * jn + 2 * lq;
                int r0 = 32 * rg + 16 * rt + g;
                float2 w0, w1;
                w0.x = MRG[r0 * 132 + d]           + o[rt][jn][0] * coef[2 * rt];
                w0.y = MRG[r0 * 132 + d + 1]       + o[rt][jn][1] * coef[2 * rt];
                w1.x = MRG[(r0 + 8) * 132 + d]     + o[rt][jn][2] * coef[2 * rt + 1];
                w1.y = MRG[(r0 + 8) * 132 + d + 1] + o[rt][jn][3] * coef[2 * rt + 1];
                *reinterpret_cast<float2*>(&gout[gbase + (size_t)(q0 + r0) * kD + d])     = w0;
                *reinterpret_cast<float2*>(&gout[gbase + (size_t)(q0 + r0 + 8) * kD + d]) = w1;
            }
    }
}

extern "C" void kernel_launch(void* const* d_in, const int* in_sizes, int n_in,
                              void* d_out, int out_size) {
    (void)in_sizes; (void)n_in; (void)out_size;
    const float* q = (const float*)d_in[0];
    const float* k = (const float*)d_in[1];
    const float* v = (const float*)d_in[2];
    float* out = (float*)d_out;

    convert_kv_f16<<<kN / 4 / 256, 256>>>(k, v);

    cudaFuncSetAttribute(fa_f16_kernel,
                         cudaFuncAttributeMaxDynamicSharedMemorySize, SMEM_BYTES);
    dim3 grid(kL / BR, kBH);   // 32 q-tiles x 32 heads
    fa_f16_kernel<<<grid, NTHR, SMEM_BYTES>>>(q, out);
}

// round 16
// speedup vs baseline: 2.7870x; 1.0449x over previous
#include <cuda_runtime.h>
#include <cuda_fp16.h>
#include <cstdint>

// Causal prefill attention, q,k,v,out: [B,H,L,D] fp32. B=2 H=16 L=2048 D=128.
// Kernel 1: convert k/v fp32 -> fp16 (RN) into static device buffers.
// Kernel 2: flash-attention-2, fp16 mma.sync.m16n8k16 (fp32 accum).
// BR=64, 4 warps, 2 CTAs/SM. Warp (rg, half) = 32 query rows x 32-key half,
// per-warp online softmax, one merge at the end. P register-resident
// (GEMM1 C-fragment packs directly into the GEMM2 A-fragment).
// R16: LAZY-MAX softmax. m_used is frozen per row; a tile triggers the
// (shuffle-max + rescale) path only if some score exceeds m_used + 8
// (checked per-thread + one warp ballot). p <= 2^8 stays comfortably in
// fp16; l and O accumulate in fp32, all consistently scaled by
// ex2(-m_used). After the first real tile the rescale path ~never fires:
// the serial shfl-max chain and the 136-FMUL rescale leave the hot loop.
// K/V double-buffered via cp.async; Q/K/V operands ldmatrix-fed.
// Q converted + pre-scaled by log2(e)/sqrt(D) inline. Row-sum l via
// MMA-with-ones on the packed P fragments.

namespace {
constexpr int kL = 2048, kD = 128, kBH = 32;
constexpr int BR = 64, BC = 64, NTHR = 128;
constexpr int kN = kBH * kL * kD;
constexpr float kScaleLog2 = 0.12751745210670913f;  // (1/sqrt(128))*log2(e)
constexpr float kMInit = -60.0f;
constexpr float kLazySlack = 8.0f;       // rescale only when beaten by > 8 (p <= 256)
constexpr uint32_t ONE2 = 0x3C003C00u;   // half2(1.0, 1.0)

// fp16 smem strides (halves) and byte offsets
constexpr int TSTR = 136;   // 272 B == 16 mod 128 -> ldsm conflict-free
constexpr int B_Q  = 0;                     // 64*272 = 17408
constexpr int B_K0 = 17408;
constexpr int B_K1 = 34816;
constexpr int B_V0 = 52224;
constexpr int B_V1 = 69632;
constexpr int B_ML = 87040;                 // 256 f32 = 1024
constexpr int SMEM_BYTES = 88064;           // x2 CTAs = 176128 <= 228KB/SM
constexpr int B_MRG = B_K0;                 // epilogue merge: 33792 B, fits K0+K1
}

__device__ __half g_k16[kN];
__device__ __half g_v16[kN];

__global__ void convert_kv_f16(const float* __restrict__ k,
                               const float* __restrict__ v) {
    int i = blockIdx.x * blockDim.x + threadIdx.x;   // 0 .. kN/4-1
    float4 a = reinterpret_cast<const float4*>(k)[i];
    float4 b = reinterpret_cast<const float4*>(v)[i];
    __half2 a0 = __floats2half2_rn(a.x, a.y), a1 = __floats2half2_rn(a.z, a.w);
    __half2 b0 = __floats2half2_rn(b.x, b.y), b1 = __floats2half2_rn(b.z, b.w);
    uint2 wa, wb;
    wa.x = *reinterpret_cast<uint32_t*>(&a0); wa.y = *reinterpret_cast<uint32_t*>(&a1);
    wb.x = *reinterpret_cast<uint32_t*>(&b0); wb.y = *reinterpret_cast<uint32_t*>(&b1);
    reinterpret_cast<uint2*>(g_k16)[i] = wa;
    reinterpret_cast<uint2*>(g_v16)[i] = wb;
}

__device__ __forceinline__ float fast_ex2(float x) {
    float y;
    asm("ex2.approx.f32 %0, %1;" : "=f"(y) : "f"(x));
    return y;
}
__device__ __forceinline__ uint32_t smem_u32(const void* p) {
    uint32_t a;
    asm("{ .reg .u64 t; cvta.to.shared.u64 t, %1; cvt.u32.u64 %0, t; }" : "=r"(a) : "l"(p));
    return a;
}
__device__ __forceinline__ void ldsm_x4(uint32_t r[4], uint32_t addr) {
    asm volatile("ldmatrix.sync.aligned.m8n8.x4.shared.b16 {%0,%1,%2,%3}, [%4];"
                 : "=r"(r[0]), "=r"(r[1]), "=r"(r[2]), "=r"(r[3]) : "r"(addr));
}
__device__ __forceinline__ void ldsm_x4_t(uint32_t r[4], uint32_t addr) {
    asm volatile("ldmatrix.sync.aligned.m8n8.x4.trans.shared.b16 {%0,%1,%2,%3}, [%4];"
                 : "=r"(r[0]), "=r"(r[1]), "=r"(r[2]), "=r"(r[3]) : "r"(addr));
}
__device__ __forceinline__ void mma_f16(float c[4], const uint32_t a[4],
                                        uint32_t b0, uint32_t b1) {
    asm volatile(
        "mma.sync.aligned.m16n8k16.row.col.f32.f16.f16.f32 "
        "{%0,%1,%2,%3}, {%4,%5,%6,%7}, {%8,%9}, {%0,%1,%2,%3};\n"
        : "+f"(c[0]), "+f"(c[1]), "+f"(c[2]), "+f"(c[3])
        : "r"(a[0]), "r"(a[1]), "r"(a[2]), "r"(a[3]), "r"(b0), "r"(b1));
}

// async-stage one 64x128 fp16 tile (16B copies)
__device__ __forceinline__ void stage_tile16(uint32_t dst, const __half* __restrict__ src,
                                             int k0, int tid) {
    #pragma unroll
    for (int i = 0; i < 8; ++i) {
        int lin = tid + i * NTHR;
        int r = lin >> 4, c = lin & 15;
        const __half* p = src + (size_t)(k0 + r) * kD + c * 8;
        uint32_t d = dst + (uint32_t)(r * (TSTR * 2) + c * 16);
        asm volatile("cp.async.ca.shared.global [%0], [%1], 16;" :: "r"(d), "l"(p));
    }
}

__global__ __launch_bounds__(NTHR, 2)
void fa_f16_kernel(const float* __restrict__ gqf, float* __restrict__ gout) {
    extern __shared__ char smem[];
    const uint32_t sb = smem_u32(smem);
    float* MLp = reinterpret_cast<float*>(smem + B_ML);
    float* MRG = reinterpret_cast<float*>(smem + B_MRG);

    const int tid  = threadIdx.x;
    const int lane = tid & 31;
    const int wid  = tid >> 5;           // 0..3
    const int rg   = wid >> 1;           // row-group 0..1 (32 rows each)
    const int half = wid & 1;            // key half within each BC tile
    const int g    = lane >> 2;
    const int lq   = lane & 3;
    const int l15  = lane & 15;

    // ---- ldmatrix base addresses (bytes) ----
    const int chi = (lane >> 4) & 1;
    const uint32_t qA0 = sb + B_Q + (uint32_t)((32 * rg + l15) * (TSTR * 2) + chi * 16);
    const uint32_t qA1 = qA0 + (uint32_t)(16 * TSTR * 2);
    const uint32_t krel = (uint32_t)((32 * half + ((lane >> 4) << 3) + (lane & 7)) * (TSTR * 2)
                                     + ((lane >> 3) & 1) * 16);
    const uint32_t vrel = (uint32_t)((32 * half + l15) * (TSTR * 2) + ((lane >> 4) & 1) * 16);

    const int it = (int)gridDim.x - 1 - (int)blockIdx.x;   // heavy tiles first
    const int bh = blockIdx.y;
    const size_t base = (size_t)bh * kL * kD;
    const int q0 = it * BR;
    const __half* gk = g_k16 + base;
    const __half* gv = g_v16 + base;

    // ---- prologue: stage K(0)/V(0) async; convert+prescale Q inline ----
    stage_tile16(sb + B_K0, gk, 0, tid);
    stage_tile16(sb + B_V0, gv, 0, tid);
    asm volatile("cp.async.commit_group;" ::: "memory");

    {
        __half* Qh = reinterpret_cast<__half*>(smem + B_Q);
        const float* qsrc = gqf + base;
        #pragma unroll
        for (int i = 0; i < 16; ++i) {       // 64x128 f32 -> fp16 (prescaled)
            int lin = tid + i * NTHR;
            int r = lin >> 5, c4 = (lin & 31) << 2;
            float4 t = *reinterpret_cast<const float4*>(&qsrc[(size_t)(q0 + r) * kD + c4]);
            __half2 h0 = __floats2half2_rn(t.x * kScaleLog2, t.y * kScaleLog2);
            __half2 h1 = __floats2half2_rn(t.z * kScaleLog2, t.w * kScaleLog2);
            uint2 w;
            w.x = *reinterpret_cast<uint32_t*>(&h0);
            w.y = *reinterpret_cast<uint32_t*>(&h1);
            *reinterpret_cast<uint2*>(&Qh[r * TSTR + c4]) = w;
        }
    }

    float o[2][16][4];
    #pragma unroll
    for (int rt = 0; rt < 2; ++rt)
        #pragma unroll
        for (int jn = 0; jn < 16; ++jn)
            { o[rt][jn][0] = o[rt][jn][1] = o[rt][jn][2] = o[rt][jn][3] = 0.f; }
    float lacc[2][4];                     // row-sum fragments (MMA-with-ones)
    lacc[0][0] = lacc[0][1] = lacc[0][2] = lacc[0][3] = 0.f;
    lacc[1][0] = lacc[1][1] = lacc[1][2] = lacc[1][3] = 0.f;
    float mm[4] = {kMInit, kMInit, kMInit, kMInit};   // frozen reference maxes

    const int njt = it + 1;
    for (int jt = 0; jt < njt; ++jt) {
        const int k0 = jt * BC;

        asm volatile("cp.async.wait_group 0;" ::: "memory");   // K(jt),V(jt) resident
        __syncthreads();   // also covers Q visibility on jt==0

        if (jt + 1 < njt) {
            stage_tile16(sb + ((jt & 1) ? B_K0 : B_K1), gk, k0 + BC, tid);
            stage_tile16(sb + ((jt & 1) ? B_V0 : B_V1), gv, k0 + BC, tid);
            asm volatile("cp.async.commit_group;" ::: "memory");
        }

        const uint32_t kB = sb + (uint32_t)((jt & 1) ? B_K1 : B_K0) + krel;
        const uint32_t vB = sb + (uint32_t)((jt & 1) ? B_V1 : B_V0) + vrel;

        // ---- GEMM1: S[32 x 32] = Q' x K(half)^T (already log2-scaled) ----
        float s[2][4][4];
        #pragma unroll
        for (int rt = 0; rt < 2; ++rt)
            #pragma unroll
            for (int j = 0; j < 4; ++j)
                { s[rt][j][0] = s[rt][j][1] = s[rt][j][2] = s[rt][j][3] = 0.f; }

        #pragma unroll
        for (int kk = 0; kk < 8; ++kk) {
            uint32_t A0[4], A1[4], B0[4], B1[4];
            ldsm_x4(A0, qA0 + kk * 32u);
            ldsm_x4(A1, qA1 + kk * 32u);
            ldsm_x4(B0, kB + kk * 32u);
            ldsm_x4(B1, kB + 16u * (TSTR * 2) + kk * 32u);
            mma_f16(s[0][0], A0, B0[0], B0[1]);
            mma_f16(s[0][1], A0, B0[2], B0[3]);
            mma_f16(s[0][2], A0, B1[0], B1[1]);
            mma_f16(s[0][3], A0, B1[2], B1[3]);
            mma_f16(s[1][0], A1, B0[0], B0[1]);
            mma_f16(s[1][1], A1, B0[2], B0[3]);
            mma_f16(s[1][2], A1, B1[0], B1[1]);
            mma_f16(s[1][3], A1, B1[2], B1[3]);
        }

        // ---- warp-local LAZY softmax (log2 domain); P packed to A-fragments ----
        const bool diag = (jt == it);
        uint32_t pa[2][2][4];   // [rt][key chunk kk][a0..a3]
        #pragma unroll
        for (int rt = 0; rt < 2; ++rt) {
            const int r0 = q0 + 32 * rg + 16 * rt + g, r1 = r0 + 8;
            float t0 = -1e30f, t1 = -1e30f;
            #pragma unroll
            for (int j = 0; j < 4; ++j) {
                if (diag) {
                    int col = k0 + 32 * half + 8 * j + 2 * lq;
                    if (col     > r0) s[rt][j][0] = -1e30f;
                    if (col + 1 > r0) s[rt][j][1] = -1e30f;
                    if (col     > r1) s[rt][j][2] = -1e30f;
                    if (col + 1 > r1) s[rt][j][3] = -1e30f;
                }
                t0 = fmaxf(t0, fmaxf(s[rt][j][0], s[rt][j][1]));
                t1 = fmaxf(t1, fmaxf(s[rt][j][2], s[rt][j][3]));
            }

            float mu0 = mm[2 * rt], mu1 = mm[2 * rt + 1];
            // rescale only if this tile beats the frozen reference by > slack
            const bool exceed = (t0 > mu0 + kLazySlack) || (t1 > mu1 + kLazySlack);
            if (__any_sync(0xffffffffu, exceed)) {
                // rare path: true row max via shuffles, rescale O / lacc
                t0 = fmaxf(t0, __shfl_xor_sync(0xffffffffu, t0, 1));
                t0 = fmaxf(t0, __shfl_xor_sync(0xffffffffu, t0, 2));
                t1 = fmaxf(t1, __shfl_xor_sync(0xffffffffu, t1, 1));
                t1 = fmaxf(t1, __shfl_xor_sync(0xffffffffu, t1, 2));
                const float mn0 = fmaxf(mu0, t0), mn1 = fmaxf(mu1, t1);
                const float al0 = fast_ex2(mu0 - mn0), al1 = fast_ex2(mu1 - mn1);
                mm[2 * rt] = mn0; mm[2 * rt + 1] = mn1;
                mu0 = mn0; mu1 = mn1;
                lacc[rt][0] *= al0; lacc[rt][1] *= al0;
                lacc[rt][2] *= al1; lacc[rt][3] *= al1;
                #pragma unroll
                for (int jn = 0; jn < 16; ++jn) {
                    o[rt][jn][0] *= al0; o[rt][jn][1] *= al0;
                    o[rt][jn][2] *= al1; o[rt][jn][3] *= al1;
                }
            }

            // exp + pack: C-fragment (rows g,g+8; cols 8j+2lq,+1) -> A-fragment
            //   chunk kk = j>>1;  j even -> a0/a1,  j odd -> a2/a3
            #pragma unroll
            for (int j = 0; j < 4; ++j) {
                float p0 = fast_ex2(s[rt][j][0] - mu0);
                float p1 = fast_ex2(s[rt][j][1] - mu0);
                float p2 = fast_ex2(s[rt][j][2] - mu1);
                float p3 = fast_ex2(s[rt][j][3] - mu1);
                __half2 h0 = __floats2half2_rn(p0, p1);   // row g
                __half2 h1 = __floats2half2_rn(p2, p3);   // row g+8
                pa[rt][j >> 1][(j & 1) * 2]     = *reinterpret_cast<uint32_t*>(&h0);
                pa[rt][j >> 1][(j & 1) * 2 + 1] = *reinterpret_cast<uint32_t*>(&h1);
            }
        }

        // ---- GEMM2: O[32 x 128] += P(32x32) x V(half keys); l += P x ones ----
        #pragma unroll
        for (int kk = 0; kk < 2; ++kk) {
            mma_f16(lacc[0], pa[0][kk], ONE2, ONE2);   // exact fp16 row-sums of P
            mma_f16(lacc[1], pa[1][kk], ONE2, ONE2);
            const uint32_t vkk = vB + (uint32_t)(kk * 16 * (TSTR * 2));
            #pragma unroll
            for (int jp = 0; jp < 8; ++jp) {
                uint32_t VB[4];
                ldsm_x4_t(VB, vkk + jp * 32u);
                mma_f16(o[0][2 * jp],     pa[0][kk], VB[0], VB[1]);
                mma_f16(o[0][2 * jp + 1], pa[0][kk], VB[2], VB[3]);
                mma_f16(o[1][2 * jp],     pa[1][kk], VB[0], VB[1]);
                mma_f16(o[1][2 * jp + 1], pa[1][kk], VB[2], VB[3]);
            }
        }
    }

    // ================= final merge of the two key-halves =================
    // ll[i] for i = 2rt + rh lives in lacc[rt][2*rh] (columns duplicated)
    if (lq == 0) {
        #pragma unroll
        for (int i = 0; i < 4; ++i) {
            int rloc = 32 * rg + 16 * (i >> 1) + g + 8 * (i & 1);
            MLp[half * 128 + 2 * rloc]     = mm[i];
            MLp[half * 128 + 2 * rloc + 1] = lacc[i >> 1][(i & 1) * 2];
        }
    }
    __syncthreads();
    float coef[4];
    #pragma unroll
    for (int i = 0; i < 4; ++i) {
        int rloc = 32 * rg + 16 * (i >> 1) + g + 8 * (i & 1);
        float mo = MLp[(1 - half) * 128 + 2 * rloc];
        float lo = MLp[(1 - half) * 128 + 2 * rloc + 1];
        float ms = fmaxf(mm[i], mo);
        float lt = lacc[i >> 1][(i & 1) * 2] * fast_ex2(mm[i] - ms) + lo * fast_ex2(mo - ms);
        coef[i] = fast_ex2(mm[i] - ms) / lt;
    }
    __syncthreads();

    if (half == 0) {
        #pragma unroll
        for (int rt = 0; rt < 2; ++rt)
            #pragma unroll
            for (int jn = 0; jn < 16; ++jn) {
                int d = 8 * jn + 2 * lq;
                int r0 = 32 * rg + 16 * rt + g;
                MRG[r0 * 132 + d]           = o[rt][jn][0] * coef[2 * rt];
                MRG[r0 * 132 + d + 1]       = o[rt][jn][1] * coef[2 * rt];
                MRG[(r0 + 8) * 132 + d]     = o[rt][jn][2] * coef[2 * rt + 1];
                MRG[(r0 + 8) * 132 + d + 1] = o[rt][jn][3] * coef[2 * rt + 1];
            }
    }
    __syncthreads();
    if (half == 1) {
        const size_t gbase = (size_t)bh * kL * kD;
        #pragma unroll
        for (int rt = 0; rt < 2; ++rt)
            #pragma unroll
            for (int jn = 0; jn < 16; ++jn) {
                int d = 8 * jn + 2 * lq;
                int r0 = 32 * rg + 16 * rt + g;
                float2 w0, w1;
                w0.x = MRG[r0 * 132 + d]           + o[rt][jn][0] * coef[2 * rt];
                w0.y = MRG[r0 * 132 + d + 1]       + o[rt][jn][1] * coef[2 * rt];
                w1.x = MRG[(r0 + 8) * 132 + d]     + o[rt][jn][2] * coef[2 * rt + 1];
                w1.y = MRG[(r0 + 8) * 132 + d + 1] + o[rt][jn][3] * coef[2 * rt + 1];
                *reinterpret_cast<float2*>(&gout[gbase + (size_t)(q0 + r0) * kD + d])     = w0;
                *reinterpret_cast<float2*>(&gout[gbase + (size_t)(q0 + r0 + 8) * kD + d]) = w1;
            }
    }
}

extern "C" void kernel_launch(void* const* d_in, const int* in_sizes, int n_in,
                              void* d_out, int out_size) {
    (void)in_sizes; (void)n_in; (void)out_size;
    const float* q = (const float*)d_in[0];
    const float* k = (const float*)d_in[1];
    const float* v = (const float*)d_in[2];
    float* out = (float*)d_out;

    convert_kv_f16<<<kN / 4 / 256, 256>>>(k, v);

    cudaFuncSetAttribute(fa_f16_kernel,
                         cudaFuncAttributeMaxDynamicSharedMemorySize, SMEM_BYTES);
    dim3 grid(kL / BR, kBH);   // 32 q-tiles x 32 heads
    fa_f16_kernel<<<grid, NTHR, SMEM_BYTES>>>(q, out);
}